// round 3
// baseline (speedup 1.0000x reference)
#include <cuda_runtime.h>
#include <cstdint>
#include <math.h>

// Problem constants
#define TOKS 8192          // B*N
#define DIMM 768
#define HIDM 3072
#define NBATCH 8
#define NSEQ 1024
#define NHEADS 12
#define HDIM 64
#define SCALEQ 0.125f      // 64^-0.5

// ---------------- scratch (static device allocations; no cudaMalloc allowed) ----
__device__ float g_h [TOKS*DIMM];
__device__ float g_q [96*NSEQ*HDIM];
__device__ float g_k [96*NSEQ*HDIM];
__device__ float g_v [96*NSEQ*HDIM];
__device__ float g_o [TOKS*DIMM];
__device__ float g_x1[TOKS*DIMM];
__device__ float g_h2[TOKS*DIMM];
__device__ float g_mi[TOKS*HIDM];

// ---------------- helpers ----------------
__device__ __forceinline__ uint32_t f2tf(float f){
  uint32_t u; asm("cvt.rna.tf32.f32 %0, %1;" : "=r"(u) : "f"(f)); return u;
}
__device__ __forceinline__ void mma_tf32(float c[4], const uint32_t a[4], uint32_t b0, uint32_t b1){
  asm volatile("mma.sync.aligned.m16n8k8.row.col.f32.tf32.tf32.f32 "
      "{%0,%1,%2,%3},{%4,%5,%6,%7},{%8,%9},{%0,%1,%2,%3};"
      : "+f"(c[0]), "+f"(c[1]), "+f"(c[2]), "+f"(c[3])
      : "r"(a[0]), "r"(a[1]), "r"(a[2]), "r"(a[3]), "r"(b0), "r"(b1));
}
__device__ __forceinline__ void sts4(uint32_t* p, float4 v){
  p[0]=f2tf(v.x); p[1]=f2tf(v.y); p[2]=f2tf(v.z); p[3]=f2tf(v.w);
}
__device__ __forceinline__ float gelu_exact(float x){
  return 0.5f * x * (1.0f + erff(x * 0.70710678118654752f));
}

// ---------------- LayerNorm: one row (768) per block, 256 threads ----------------
__global__ __launch_bounds__(256) void ln_kernel(const float* __restrict__ x,
    const float* __restrict__ gam, const float* __restrict__ bet, float* __restrict__ out){
  __shared__ float red[2][8];
  int row = blockIdx.x, tid = threadIdx.x;
  const float* xr = x + (size_t)row*DIMM;
  float v0 = xr[tid], v1 = xr[tid+256], v2 = xr[tid+512];
  float s = v0+v1+v2;
  float q = v0*v0 + v1*v1 + v2*v2;
  #pragma unroll
  for (int o=16;o;o>>=1){ s += __shfl_xor_sync(0xffffffffu, s, o); q += __shfl_xor_sync(0xffffffffu, q, o); }
  int wid = tid>>5, lane = tid&31;
  if (lane==0){ red[0][wid]=s; red[1][wid]=q; }
  __syncthreads();
  if (tid < 32){
    s = (lane<8)? red[0][lane] : 0.f;
    q = (lane<8)? red[1][lane] : 0.f;
    #pragma unroll
    for (int o=4;o;o>>=1){ s += __shfl_xor_sync(0xffffffffu, s, o); q += __shfl_xor_sync(0xffffffffu, q, o); }
    if (lane==0){ red[0][0]=s; red[1][0]=q; }
  }
  __syncthreads();
  float mu  = red[0][0] * (1.f/(float)DIMM);
  float var = red[1][0] * (1.f/(float)DIMM) - mu*mu;
  float rs = rsqrtf(var + 1e-5f);
  float* orow = out + (size_t)row*DIMM;
  orow[tid]     = (v0-mu)*rs*gam[tid]     + bet[tid];
  orow[tid+256] = (v1-mu)*rs*gam[tid+256] + bet[tid+256];
  orow[tid+512] = (v2-mu)*rs*gam[tid+512] + bet[tid+512];
}

// ---------------- generic tf32 GEMM: out[M,Nc] = A[M,K] @ W[Nc,K]^T + epi ------
// tile 128x128xBK16, 256 threads, 8 warps (2x4), warp tile 64x32
// MODE 0: out = acc + bias + res    MODE 1: out = gelu(acc + bias)
template<int MODE>
__global__ __launch_bounds__(256) void gemm_tf32(
    const float* __restrict__ A, const float* __restrict__ W,
    const float* __restrict__ bias, const float* __restrict__ res,
    float* __restrict__ out, int Nc, int K){
  __shared__ uint32_t As[2][128][20];
  __shared__ uint32_t Bs[2][128][20];
  int tid = threadIdx.x;
  int warp = tid>>5, lane = tid&31, g = lane>>2, t = lane&3;
  int wm = warp>>2, wn = warp&3;
  int bm = blockIdx.y*128, bn = blockIdx.x*128;

  int lr = tid>>2, lc = tid&3;   // loader: rows lr and lr+64, float4 group lc
  const float* aptr0 = A + (size_t)(bm+lr)*K + lc*4;
  const float* aptr1 = aptr0 + (size_t)64*K;
  const float* bptr0 = W + (size_t)(bn+lr)*K + lc*4;
  const float* bptr1 = bptr0 + (size_t)64*K;

  float acc[4][4][4];
  #pragma unroll
  for (int i=0;i<4;i++)
    #pragma unroll
    for (int j=0;j<4;j++)
      #pragma unroll
      for (int kx=0;kx<4;kx++) acc[i][j][kx]=0.f;

  float4 ra0 = *(const float4*)aptr0;
  float4 ra1 = *(const float4*)aptr1;
  float4 rb0 = *(const float4*)bptr0;
  float4 rb1 = *(const float4*)bptr1;
  sts4(&As[0][lr][lc*4],    ra0);
  sts4(&As[0][lr+64][lc*4], ra1);
  sts4(&Bs[0][lr][lc*4],    rb0);
  sts4(&Bs[0][lr+64][lc*4], rb1);
  __syncthreads();

  int KT = K >> 4;
  int buf = 0;
  for (int kt=0; kt<KT; kt++){
    if (kt+1 < KT){
      ra0 = *(const float4*)(aptr0 + (kt+1)*16);
      ra1 = *(const float4*)(aptr1 + (kt+1)*16);
      rb0 = *(const float4*)(bptr0 + (kt+1)*16);
      rb1 = *(const float4*)(bptr1 + (kt+1)*16);
    }
    #pragma unroll
    for (int kk=0; kk<2; kk++){
      uint32_t af[4][4]; uint32_t bf[4][2];
      #pragma unroll
      for (int mt=0;mt<4;mt++){
        int r = wm*64 + mt*16;
        af[mt][0] = As[buf][r+g][kk*8+t];
        af[mt][1] = As[buf][r+g+8][kk*8+t];
        af[mt][2] = As[buf][r+g][kk*8+t+4];
        af[mt][3] = As[buf][r+g+8][kk*8+t+4];
      }
      #pragma unroll
      for (int nt=0;nt<4;nt++){
        int n = wn*32 + nt*8;
        bf[nt][0] = Bs[buf][n+g][kk*8+t];
        bf[nt][1] = Bs[buf][n+g][kk*8+t+4];
      }
      #pragma unroll
      for (int mt=0;mt<4;mt++)
        #pragma unroll
        for (int nt=0;nt<4;nt++)
          mma_tf32(acc[mt][nt], af[mt], bf[nt][0], bf[nt][1]);
    }
    if (kt+1 < KT){
      int nb = buf^1;
      sts4(&As[nb][lr][lc*4],    ra0);
      sts4(&As[nb][lr+64][lc*4], ra1);
      sts4(&Bs[nb][lr][lc*4],    rb0);
      sts4(&Bs[nb][lr+64][lc*4], rb1);
    }
    __syncthreads();
    buf ^= 1;
  }

  #pragma unroll
  for (int mt=0;mt<4;mt++){
    int row = bm + wm*64 + mt*16 + g;
    #pragma unroll
    for (int nt=0;nt<4;nt++){
      int col = bn + wn*32 + nt*8 + 2*t;
      float b0v = bias[col], b1v = bias[col+1];
      float v00 = acc[mt][nt][0] + b0v, v01 = acc[mt][nt][1] + b1v;
      float v10 = acc[mt][nt][2] + b0v, v11 = acc[mt][nt][3] + b1v;
      if (MODE==0){
        const float* r0 = res + (size_t)row*Nc + col;
        const float* r1 = res + (size_t)(row+8)*Nc + col;
        v00 += r0[0]; v01 += r0[1]; v10 += r1[0]; v11 += r1[1];
      } else {
        v00 = gelu_exact(v00); v01 = gelu_exact(v01);
        v10 = gelu_exact(v10); v11 = gelu_exact(v11);
      }
      *(float2*)(out + (size_t)row*Nc + col)     = make_float2(v00,v01);
      *(float2*)(out + (size_t)(row+8)*Nc + col) = make_float2(v10,v11);
    }
  }
}

// ---------------- fused QKV GEMM: Nc=2304 = [kv 1536 | shared_q 704 | cohort 64]
__global__ __launch_bounds__(256) void qkv_kernel(
    const float* __restrict__ A,
    const float* __restrict__ kv_w, const float* __restrict__ sq_w, const float* __restrict__ cq_w,
    const float* __restrict__ kv_b, const float* __restrict__ sq_b, const float* __restrict__ cq_b,
    const int* __restrict__ cvals,
    float* __restrict__ qo, float* __restrict__ ko, float* __restrict__ vo){
  __shared__ uint32_t As[2][128][20];
  __shared__ uint32_t Bs[2][128][20];
  const int K = DIMM;
  int tid = threadIdx.x;
  int warp = tid>>5, lane = tid&31, g = lane>>2, t = lane&3;
  int wm = warp>>2, wn = warp&3;
  int bm = blockIdx.y*128, bn = blockIdx.x*128;
  int bb = blockIdx.y >> 3;           // batch (1024/128 = 8 M-tiles per batch)
  int coh = cvals[bb];

  int lr = tid>>2, lc = tid&3;
  const float* aptr0 = A + (size_t)(bm+lr)*K + lc*4;
  const float* aptr1 = aptr0 + (size_t)64*K;
  // B row source select (gathered weight rows)
  int j0 = bn + lr, j1 = j0 + 64;
  const float* bptr0;
  const float* bptr1;
  if (j0 < 1536)       bptr0 = kv_w + (size_t)j0*K;
  else if (j0 < 2240)  bptr0 = sq_w + (size_t)(j0-1536)*K;
  else                 bptr0 = cq_w + ((size_t)coh*64 + (j0-2240))*K;
  if (j1 < 1536)       bptr1 = kv_w + (size_t)j1*K;
  else if (j1 < 2240)  bptr1 = sq_w + (size_t)(j1-1536)*K;
  else                 bptr1 = cq_w + ((size_t)coh*64 + (j1-2240))*K;
  bptr0 += lc*4; bptr1 += lc*4;

  float acc[4][4][4];
  #pragma unroll
  for (int i=0;i<4;i++)
    #pragma unroll
    for (int j=0;j<4;j++)
      #pragma unroll
      for (int kx=0;kx<4;kx++) acc[i][j][kx]=0.f;

  float4 ra0 = *(const float4*)aptr0;
  float4 ra1 = *(const float4*)aptr1;
  float4 rb0 = *(const float4*)bptr0;
  float4 rb1 = *(const float4*)bptr1;
  sts4(&As[0][lr][lc*4],    ra0);
  sts4(&As[0][lr+64][lc*4], ra1);
  sts4(&Bs[0][lr][lc*4],    rb0);
  sts4(&Bs[0][lr+64][lc*4], rb1);
  __syncthreads();

  const int KT = K >> 4;  // 48
  int buf = 0;
  for (int kt=0; kt<KT; kt++){
    if (kt+1 < KT){
      ra0 = *(const float4*)(aptr0 + (kt+1)*16);
      ra1 = *(const float4*)(aptr1 + (kt+1)*16);
      rb0 = *(const float4*)(bptr0 + (kt+1)*16);
      rb1 = *(const float4*)(bptr1 + (kt+1)*16);
    }
    #pragma unroll
    for (int kk=0; kk<2; kk++){
      uint32_t af[4][4]; uint32_t bf[4][2];
      #pragma unroll
      for (int mt=0;mt<4;mt++){
        int r = wm*64 + mt*16;
        af[mt][0] = As[buf][r+g][kk*8+t];
        af[mt][1] = As[buf][r+g+8][kk*8+t];
        af[mt][2] = As[buf][r+g][kk*8+t+4];
        af[mt][3] = As[buf][r+g+8][kk*8+t+4];
      }
      #pragma unroll
      for (int nt=0;nt<4;nt++){
        int n = wn*32 + nt*8;
        bf[nt][0] = Bs[buf][n+g][kk*8+t];
        bf[nt][1] = Bs[buf][n+g][kk*8+t+4];
      }
      #pragma unroll
      for (int mt=0;mt<4;mt++)
        #pragma unroll
        for (int nt=0;nt<4;nt++)
          mma_tf32(acc[mt][nt], af[mt], bf[nt][0], bf[nt][1]);
    }
    if (kt+1 < KT){
      int nb = buf^1;
      sts4(&As[nb][lr][lc*4],    ra0);
      sts4(&As[nb][lr+64][lc*4], ra1);
      sts4(&Bs[nb][lr][lc*4],    rb0);
      sts4(&Bs[nb][lr+64][lc*4], rb1);
    }
    __syncthreads();
    buf ^= 1;
  }

  // epilogue: scatter into q/k/v [B*H, N, 64] with bias
  #pragma unroll
  for (int mt=0;mt<4;mt++){
    int row = bm + wm*64 + mt*16 + g;
    int n = row & 1023;
    #pragma unroll
    for (int nt=0;nt<4;nt++){
      int col = bn + wn*32 + nt*8 + 2*t;
      float bias0, bias1;
      float* dst;
      if (col < 1536){
        int part = (col >= 768) ? 1 : 0;
        int cc = col - part*768;
        int head = cc >> 6, hd = cc & 63;
        dst = (part ? vo : ko) + ((size_t)(bb*NHEADS + head)*NSEQ + n)*HDIM + hd;
        bias0 = kv_b[col]; bias1 = kv_b[col+1];
      } else if (col < 2240){
        int cc = col - 1536;
        int head = cc >> 6, hd = cc & 63;
        dst = qo + ((size_t)(bb*NHEADS + head)*NSEQ + n)*HDIM + hd;
        bias0 = sq_b[cc]; bias1 = sq_b[cc+1];
      } else {
        int hd = col - 2240;
        dst = qo + ((size_t)(bb*NHEADS + 11)*NSEQ + n)*HDIM + hd;
        bias0 = cq_b[coh*64 + hd]; bias1 = cq_b[coh*64 + hd + 1];
      }
      dst[0] = acc[mt][nt][0] + bias0;
      dst[1] = acc[mt][nt][1] + bias1;
      float* dst2 = dst + 8*HDIM;   // row+8 -> n+8, same batch/head
      dst2[0] = acc[mt][nt][2] + bias0;
      dst2[1] = acc[mt][nt][3] + bias1;
    }
  }
}

// ---------------- flash attention (tf32 mma, online softmax) ----------------
// grid: (8 q-tiles, 96 bh). block: 256 threads = 8 warps; warp owns 16 Q rows.
#define KS_STRIDE 68
#define VT_STRIDE 132
#define PS_STRIDE 132
__global__ __launch_bounds__(256, 1) void attn_kernel(
    const float* __restrict__ qb, const float* __restrict__ kb,
    const float* __restrict__ vb, float* __restrict__ ob){
  extern __shared__ float smatt[];
  float* KS = smatt;                          // [128][68]
  float* VT = smatt + 128*KS_STRIDE;          // [64][132]
  float* PS = VT + 64*VT_STRIDE;              // [8 warps][16][132]
  int tid = threadIdx.x, warp = tid>>5, lane = tid&31, g = lane>>2, t = lane&3;
  int bh = blockIdx.y, qt = blockIdx.x;
  const float* Q = qb + ((size_t)bh*NSEQ + qt*128)*HDIM;
  const float* K = kb + (size_t)bh*NSEQ*HDIM;
  const float* V = vb + (size_t)bh*NSEQ*HDIM;

  // load Q (scaled, tf32) through KS, then pull A-fragments to registers
  for (int i=tid; i<128*16; i+=256){
    int r = i>>4, c = i&15;
    float4 v4 = *(const float4*)(Q + (size_t)r*HDIM + c*4);
    uint32_t* p = (uint32_t*)&KS[r*KS_STRIDE + c*4];
    p[0]=f2tf(v4.x*SCALEQ); p[1]=f2tf(v4.y*SCALEQ); p[2]=f2tf(v4.z*SCALEQ); p[3]=f2tf(v4.w*SCALEQ);
  }
  __syncthreads();
  uint32_t qa[8][4];
  {
    const uint32_t* ks = (const uint32_t*)KS;
    int r0 = warp*16 + g;
    #pragma unroll
    for (int k8=0;k8<8;k8++){
      qa[k8][0] = ks[(size_t)r0*KS_STRIDE     + k8*8 + t];
      qa[k8][1] = ks[(size_t)(r0+8)*KS_STRIDE + k8*8 + t];
      qa[k8][2] = ks[(size_t)r0*KS_STRIDE     + k8*8 + t + 4];
      qa[k8][3] = ks[(size_t)(r0+8)*KS_STRIDE + k8*8 + t + 4];
    }
  }
  __syncthreads();

  float m0=-1e30f, m1=-1e30f, l0=0.f, l1=0.f;
  float oa[8][4];
  #pragma unroll
  for (int dt=0;dt<8;dt++){ oa[dt][0]=0.f; oa[dt][1]=0.f; oa[dt][2]=0.f; oa[dt][3]=0.f; }

  for (int it=0; it<8; it++){
    const float* Kt = K + (size_t)it*128*HDIM;
    const float* Vt = V + (size_t)it*128*HDIM;
    // load K tile (tf32)
    for (int i=tid; i<128*16; i+=256){
      int r = i>>4, c = i&15;
      float4 v4 = *(const float4*)(Kt + (size_t)r*HDIM + c*4);
      uint32_t* p = (uint32_t*)&KS[r*KS_STRIDE + c*4];
      p[0]=f2tf(v4.x); p[1]=f2tf(v4.y); p[2]=f2tf(v4.z); p[3]=f2tf(v4.w);
    }
    // load V tile transposed (tf32): VT[d][n]
    {
      uint32_t* vt = (uint32_t*)VT;
      for (int i=tid; i<128*16; i+=256){
        int n = i>>4, d4 = i&15;
        float4 v4 = *(const float4*)(Vt + (size_t)n*HDIM + d4*4);
        vt[(d4*4+0)*VT_STRIDE + n] = f2tf(v4.x);
        vt[(d4*4+1)*VT_STRIDE + n] = f2tf(v4.y);
        vt[(d4*4+2)*VT_STRIDE + n] = f2tf(v4.z);
        vt[(d4*4+3)*VT_STRIDE + n] = f2tf(v4.w);
      }
    }
    __syncthreads();

    // S = Q K^T  (16 rows x 128 cols per warp)
    float s[16][4];
    #pragma unroll
    for (int nt=0;nt<16;nt++){ s[nt][0]=0.f; s[nt][1]=0.f; s[nt][2]=0.f; s[nt][3]=0.f; }
    {
      const uint32_t* ks = (const uint32_t*)KS;
      #pragma unroll
      for (int k8=0;k8<8;k8++){
        #pragma unroll
        for (int nt=0;nt<16;nt++){
          uint32_t b0 = ks[(size_t)(nt*8+g)*KS_STRIDE + k8*8 + t];
          uint32_t b1 = ks[(size_t)(nt*8+g)*KS_STRIDE + k8*8 + t + 4];
          mma_tf32(s[nt], qa[k8], b0, b1);
        }
      }
    }
    // online softmax
    float mx0 = -1e30f, mx1 = -1e30f;
    #pragma unroll
    for (int nt=0;nt<16;nt++){
      mx0 = fmaxf(mx0, fmaxf(s[nt][0], s[nt][1]));
      mx1 = fmaxf(mx1, fmaxf(s[nt][2], s[nt][3]));
    }
    mx0 = fmaxf(mx0, __shfl_xor_sync(0xffffffffu, mx0, 1));
    mx0 = fmaxf(mx0, __shfl_xor_sync(0xffffffffu, mx0, 2));
    mx1 = fmaxf(mx1, __shfl_xor_sync(0xffffffffu, mx1, 1));
    mx1 = fmaxf(mx1, __shfl_xor_sync(0xffffffffu, mx1, 2));
    float nm0 = fmaxf(m0, mx0), nm1 = fmaxf(m1, mx1);
    float al0 = __expf(m0 - nm0), al1 = __expf(m1 - nm1);
    m0 = nm0; m1 = nm1;
    float sum0 = 0.f, sum1 = 0.f;
    #pragma unroll
    for (int nt=0;nt<16;nt++){
      s[nt][0] = __expf(s[nt][0] - m0);
      s[nt][1] = __expf(s[nt][1] - m0);
      s[nt][2] = __expf(s[nt][2] - m1);
      s[nt][3] = __expf(s[nt][3] - m1);
      sum0 += s[nt][0] + s[nt][1];
      sum1 += s[nt][2] + s[nt][3];
    }
    l0 = l0*al0 + sum0;
    l1 = l1*al1 + sum1;
    #pragma unroll
    for (int dt=0;dt<8;dt++){
      oa[dt][0]*=al0; oa[dt][1]*=al0; oa[dt][2]*=al1; oa[dt][3]*=al1;
    }
    // P -> per-warp smem, re-fragment as A for P@V
    uint32_t* ps = (uint32_t*)(PS + (size_t)warp*16*PS_STRIDE);
    #pragma unroll
    for (int nt=0;nt<16;nt++){
      ps[(size_t)g*PS_STRIDE     + nt*8 + 2*t]     = f2tf(s[nt][0]);
      ps[(size_t)g*PS_STRIDE     + nt*8 + 2*t + 1] = f2tf(s[nt][1]);
      ps[(size_t)(g+8)*PS_STRIDE + nt*8 + 2*t]     = f2tf(s[nt][2]);
      ps[(size_t)(g+8)*PS_STRIDE + nt*8 + 2*t + 1] = f2tf(s[nt][3]);
    }
    __syncwarp();
    {
      const uint32_t* vt = (const uint32_t*)VT;
      #pragma unroll
      for (int k2=0;k2<16;k2++){
        uint32_t pa[4];
        pa[0] = ps[(size_t)g*PS_STRIDE     + k2*8 + t];
        pa[1] = ps[(size_t)(g+8)*PS_STRIDE + k2*8 + t];
        pa[2] = ps[(size_t)g*PS_STRIDE     + k2*8 + t + 4];
        pa[3] = ps[(size_t)(g+8)*PS_STRIDE + k2*8 + t + 4];
        #pragma unroll
        for (int dt=0;dt<8;dt++){
          uint32_t b0 = vt[(size_t)(dt*8+g)*VT_STRIDE + k2*8 + t];
          uint32_t b1 = vt[(size_t)(dt*8+g)*VT_STRIDE + k2*8 + t + 4];
          mma_tf32(oa[dt], pa, b0, b1);
        }
      }
    }
    __syncthreads();
  }

  l0 += __shfl_xor_sync(0xffffffffu, l0, 1);
  l0 += __shfl_xor_sync(0xffffffffu, l0, 2);
  l1 += __shfl_xor_sync(0xffffffffu, l1, 1);
  l1 += __shfl_xor_sync(0xffffffffu, l1, 2);
  float inv0 = 1.f/l0, inv1 = 1.f/l1;

  int b = bh / NHEADS, h = bh % NHEADS;
  int row0 = qt*128 + warp*16 + g;
  float* obase = ob + (size_t)b*NSEQ*DIMM + h*HDIM;
  #pragma unroll
  for (int dt=0;dt<8;dt++){
    int col = dt*8 + 2*t;
    *(float2*)(obase + (size_t)row0*DIMM + col)     = make_float2(oa[dt][0]*inv0, oa[dt][1]*inv0);
    *(float2*)(obase + (size_t)(row0+8)*DIMM + col) = make_float2(oa[dt][2]*inv1, oa[dt][3]*inv1);
  }
}

// ---------------- host ----------------
extern "C" void kernel_launch(void* const* d_in, const int* in_sizes, int n_in,
                              void* d_out, int out_size){
  const float* x      = (const float*)d_in[0];
  const int*   cvals  = (const int*)  d_in[1];
  const float* ln1_g  = (const float*)d_in[2];
  const float* ln1_b  = (const float*)d_in[3];
  const float* kv_w   = (const float*)d_in[4];
  const float* kv_b   = (const float*)d_in[5];
  const float* sq_w   = (const float*)d_in[6];
  const float* sq_b   = (const float*)d_in[7];
  const float* cq_w   = (const float*)d_in[8];
  const float* cq_b   = (const float*)d_in[9];
  const float* proj_w = (const float*)d_in[10];
  const float* proj_b = (const float*)d_in[11];
  const float* ln2_g  = (const float*)d_in[12];
  const float* ln2_b  = (const float*)d_in[13];
  const float* fc1_w  = (const float*)d_in[14];
  const float* fc1_b  = (const float*)d_in[15];
  const float* fc2_w  = (const float*)d_in[16];
  const float* fc2_b  = (const float*)d_in[17];
  float* out = (float*)d_out;

  float *h, *q, *k, *v, *o, *x1, *h2, *mi;
  cudaGetSymbolAddress((void**)&h,  g_h);
  cudaGetSymbolAddress((void**)&q,  g_q);
  cudaGetSymbolAddress((void**)&k,  g_k);
  cudaGetSymbolAddress((void**)&v,  g_v);
  cudaGetSymbolAddress((void**)&o,  g_o);
  cudaGetSymbolAddress((void**)&x1, g_x1);
  cudaGetSymbolAddress((void**)&h2, g_h2);
  cudaGetSymbolAddress((void**)&mi, g_mi);

  // 1. LN1
  ln_kernel<<<TOKS, 256>>>(x, ln1_g, ln1_b, h);
  // 2. fused QKV (+ cohort routing) -> q/k/v [B*H, N, 64]
  qkv_kernel<<<dim3(18, 64), 256>>>(h, kv_w, sq_w, cq_w, kv_b, sq_b, cq_b, cvals, q, k, v);
  // 3. attention -> o [B, N, 768]
  size_t smem = (size_t)(128*KS_STRIDE + 64*VT_STRIDE + 8*16*PS_STRIDE) * sizeof(float);
  cudaFuncSetAttribute(attn_kernel, cudaFuncAttributeMaxDynamicSharedMemorySize, (int)smem);
  attn_kernel<<<dim3(8, 96), 256, smem>>>(q, k, v, o);
  // 4. proj + residual -> x1
  gemm_tf32<0><<<dim3(6, 64), 256>>>(o, proj_w, proj_b, x, x1, DIMM, DIMM);
  // 5. LN2
  ln_kernel<<<TOKS, 256>>>(x1, ln2_g, ln2_b, h2);
  // 6. fc1 + gelu -> mi
  gemm_tf32<1><<<dim3(24, 64), 256>>>(h2, fc1_w, fc1_b, nullptr, mi, HIDM, DIMM);
  // 7. fc2 + residual -> out
  gemm_tf32<0><<<dim3(6, 64), 256>>>(mi, fc2_w, fc2_b, x1, out, DIMM, HIDM);
}

// round 8
// speedup vs baseline: 1.2050x; 1.2050x over previous
#include <cuda_runtime.h>
#include <cuda_fp16.h>
#include <cstdint>
#include <math.h>

#define TOKS 8192
#define DIMM 768
#define HIDM 3072
#define NSEQ 1024
#define NHEADS 12
#define HDIM 64
#define SCALEQ 0.125f

// ---------------- scratch ----------------
__device__ float g_h [TOKS*DIMM];
__device__ float g_q [96*NSEQ*HDIM];
__device__ float g_k [96*NSEQ*HDIM];
__device__ float g_v [96*NSEQ*HDIM];
__device__ float g_o [TOKS*DIMM];
__device__ float g_x1[TOKS*DIMM];
__device__ float g_h2[TOKS*DIMM];
__device__ float g_mi[TOKS*HIDM];

// ---------------- helpers ----------------
__device__ __forceinline__ uint32_t f2tf(float f){
  uint32_t u; asm("cvt.rna.tf32.f32 %0, %1;" : "=r"(u) : "f"(f)); return u;
}
__device__ __forceinline__ uint32_t smem_u32(const void* p){
  uint32_t a; asm("{ .reg .u64 t; cvta.to.shared.u64 t, %1; cvt.u32.u64 %0, t; }" : "=r"(a) : "l"(p));
  return a;
}
__device__ __forceinline__ float gelu_exact(float x){
  return 0.5f * x * (1.0f + erff(x * 0.70710678118654752f));
}
__device__ __forceinline__ void mma_tf32(float c[4], const uint32_t a[4], uint32_t b0, uint32_t b1){
  asm volatile("mma.sync.aligned.m16n8k8.row.col.f32.tf32.tf32.f32 "
      "{%0,%1,%2,%3},{%4,%5,%6,%7},{%8,%9},{%0,%1,%2,%3};"
      : "+f"(c[0]), "+f"(c[1]), "+f"(c[2]), "+f"(c[3])
      : "r"(a[0]), "r"(a[1]), "r"(a[2]), "r"(a[3]), "r"(b0), "r"(b1));
}
__device__ __forceinline__ void mma_fp16(float c[4], const uint32_t a[4], uint32_t b0, uint32_t b1){
  asm volatile("mma.sync.aligned.m16n8k16.row.col.f32.f16.f16.f32 "
      "{%0,%1,%2,%3},{%4,%5,%6,%7},{%8,%9},{%0,%1,%2,%3};"
      : "+f"(c[0]), "+f"(c[1]), "+f"(c[2]), "+f"(c[3])
      : "r"(a[0]), "r"(a[1]), "r"(a[2]), "r"(a[3]), "r"(b0), "r"(b1));
}
__device__ __forceinline__ void ldsm4(uint32_t r[4], uint32_t a){
  asm volatile("ldmatrix.sync.aligned.m8n8.x4.shared.b16 {%0,%1,%2,%3}, [%4];"
    : "=r"(r[0]), "=r"(r[1]), "=r"(r[2]), "=r"(r[3]) : "r"(a));
}
// pack float4 -> 4 halves (uint2) with rn
__device__ __forceinline__ uint2 f4h4(float4 v){
  __half2 h01 = __float22half2_rn(make_float2(v.x, v.y));
  __half2 h23 = __float22half2_rn(make_float2(v.z, v.w));
  uint2 u;
  u.x = *(uint32_t*)&h01;
  u.y = *(uint32_t*)&h23;
  return u;
}

// smem tile: 128 rows x 40 halves (32 data + 8 pad) = 80B stride
#define HROW 40
#define HROWB 80

// ---------------- fp16 GEMM: out[M,Nc] = A[M,K] @ W[Nc,K]^T + epi --------------
// CTA tile 128x128, BK=32, 256 threads = 8 warps (2x4), warp tile 64x32.
// MODE 0: +bias +res     MODE 1: gelu(+bias)
template<int MODE>
__global__ __launch_bounds__(256) void gemm_fp16(
    const float* __restrict__ A, const float* __restrict__ W,
    const float* __restrict__ bias, const float* __restrict__ res,
    float* __restrict__ out, int Nc, int K){
  __shared__ __half As[2][128][HROW];
  __shared__ __half Bs[2][128][HROW];
  int tid = threadIdx.x;
  int warp = tid>>5, lane = tid&31, g = lane>>2, t = lane&3;
  int wm = warp>>2, wn = warp&3;
  int bm = blockIdx.y*128, bn = blockIdx.x*128;

  int lr = tid>>1, lg = tid&1;           // loader: row lr, half-chunk lg (16 f32)
  const float* aptr = A + (size_t)(bm+lr)*K + lg*16;
  const float* bptr = W + (size_t)(bn+lr)*K + lg*16;

  uint32_t sbA = smem_u32(&As[0][0][0]);
  uint32_t sbB = smem_u32(&Bs[0][0][0]);
  const uint32_t BUF = 128*HROWB;        // bytes per buffer

  float acc[4][4][4];
  #pragma unroll
  for (int i=0;i<4;i++)
    #pragma unroll
    for (int j=0;j<4;j++){ acc[i][j][0]=0.f; acc[i][j][1]=0.f; acc[i][j][2]=0.f; acc[i][j][3]=0.f; }

  // ldmatrix address components (byte offsets within a buffer)
  uint32_t a_off[4], b_off[2];
  {
    uint32_t arow_l = (uint32_t)((lane&15));
    uint32_t acol_l = (uint32_t)((lane>>4)*16);
    #pragma unroll
    for (int mt=0;mt<4;mt++)
      a_off[mt] = (uint32_t)(wm*64 + mt*16 + arow_l)*HROWB + acol_l;
    uint32_t brow_l = (uint32_t)(((lane>>4)*8) + (lane&7));
    uint32_t bcol_l = (uint32_t)((lane&8) ? 16 : 0);
    #pragma unroll
    for (int p=0;p<2;p++)
      b_off[p] = (uint32_t)(wn*32 + p*16 + brow_l)*HROWB + bcol_l;
  }

  // preload chunk 0
  float4 ra[4], rb[4];
  #pragma unroll
  for (int e=0;e<4;e++){ ra[e] = *(const float4*)(aptr + e*4); rb[e] = *(const float4*)(bptr + e*4); }
  #pragma unroll
  for (int e=0;e<4;e++){
    *(uint2*)&As[0][lr][lg*16 + e*4] = f4h4(ra[e]);
    *(uint2*)&Bs[0][lr][lg*16 + e*4] = f4h4(rb[e]);
  }
  __syncthreads();

  int KT = K >> 5;
  for (int kt=0; kt<KT; kt++){
    int buf = kt & 1;
    uint32_t baseA = sbA + buf*BUF;
    uint32_t baseB = sbB + buf*BUF;
    if (kt+1 < KT){
      #pragma unroll
      for (int e=0;e<4;e++){
        ra[e] = *(const float4*)(aptr + (kt+1)*32 + e*4);
        rb[e] = *(const float4*)(bptr + (kt+1)*32 + e*4);
      }
    }
    #pragma unroll
    for (int kk=0; kk<2; kk++){
      uint32_t kb = kk*32;
      uint32_t af[4][4], bf[2][4];
      #pragma unroll
      for (int mt=0;mt<4;mt++) ldsm4(af[mt], baseA + a_off[mt] + kb);
      #pragma unroll
      for (int p=0;p<2;p++)    ldsm4(bf[p],  baseB + b_off[p] + kb);
      #pragma unroll
      for (int mt=0;mt<4;mt++){
        mma_fp16(acc[mt][0], af[mt], bf[0][0], bf[0][1]);
        mma_fp16(acc[mt][1], af[mt], bf[0][2], bf[0][3]);
        mma_fp16(acc[mt][2], af[mt], bf[1][0], bf[1][1]);
        mma_fp16(acc[mt][3], af[mt], bf[1][2], bf[1][3]);
      }
    }
    if (kt+1 < KT){
      int nb = buf^1;
      #pragma unroll
      for (int e=0;e<4;e++){
        *(uint2*)&As[nb][lr][lg*16 + e*4] = f4h4(ra[e]);
        *(uint2*)&Bs[nb][lr][lg*16 + e*4] = f4h4(rb[e]);
      }
    }
    __syncthreads();
  }

  #pragma unroll
  for (int mt=0;mt<4;mt++){
    int row = bm + wm*64 + mt*16 + g;
    #pragma unroll
    for (int nt=0;nt<4;nt++){
      int col = bn + wn*32 + nt*8 + 2*t;
      float b0v = bias[col], b1v = bias[col+1];
      float v00 = acc[mt][nt][0] + b0v, v01 = acc[mt][nt][1] + b1v;
      float v10 = acc[mt][nt][2] + b0v, v11 = acc[mt][nt][3] + b1v;
      if (MODE==0){
        const float* r0 = res + (size_t)row*Nc + col;
        const float* r1 = res + (size_t)(row+8)*Nc + col;
        v00 += r0[0]; v01 += r0[1]; v10 += r1[0]; v11 += r1[1];
      } else {
        v00 = gelu_exact(v00); v01 = gelu_exact(v01);
        v10 = gelu_exact(v10); v11 = gelu_exact(v11);
      }
      *(float2*)(out + (size_t)row*Nc + col)     = make_float2(v00,v01);
      *(float2*)(out + (size_t)(row+8)*Nc + col) = make_float2(v10,v11);
    }
  }
}

// ---------------- fp16 fused QKV: Nc=2304 = [kv 1536 | sq 704 | cohort 64] ------
__global__ __launch_bounds__(256) void qkv_fp16(
    const float* __restrict__ A,
    const float* __restrict__ kv_w, const float* __restrict__ sq_w, const float* __restrict__ cq_w,
    const float* __restrict__ kv_b, const float* __restrict__ sq_b, const float* __restrict__ cq_b,
    const int* __restrict__ cvals,
    float* __restrict__ qo, float* __restrict__ ko, float* __restrict__ vo){
  __shared__ __half As[2][128][HROW];
  __shared__ __half Bs[2][128][HROW];
  const int K = DIMM;
  int tid = threadIdx.x;
  int warp = tid>>5, lane = tid&31, g = lane>>2, t = lane&3;
  int wm = warp>>2, wn = warp&3;
  int bm = blockIdx.y*128, bn = blockIdx.x*128;
  int bb = bm >> 10;
  int coh = cvals[bb];

  int lr = tid>>1, lg = tid&1;
  const float* aptr = A + (size_t)(bm+lr)*K + lg*16;
  int j = bn + lr;
  const float* bptr;
  if (j < 1536)      bptr = kv_w + (size_t)j*K;
  else if (j < 2240) bptr = sq_w + (size_t)(j-1536)*K;
  else               bptr = cq_w + ((size_t)coh*64 + (j-2240))*K;
  bptr += lg*16;

  uint32_t sbA = smem_u32(&As[0][0][0]);
  uint32_t sbB = smem_u32(&Bs[0][0][0]);
  const uint32_t BUF = 128*HROWB;

  float acc[4][4][4];
  #pragma unroll
  for (int i=0;i<4;i++)
    #pragma unroll
    for (int jx=0;jx<4;jx++){ acc[i][jx][0]=0.f; acc[i][jx][1]=0.f; acc[i][jx][2]=0.f; acc[i][jx][3]=0.f; }

  uint32_t a_off[4], b_off[2];
  {
    uint32_t arow_l = (uint32_t)((lane&15));
    uint32_t acol_l = (uint32_t)((lane>>4)*16);
    #pragma unroll
    for (int mt=0;mt<4;mt++)
      a_off[mt] = (uint32_t)(wm*64 + mt*16 + arow_l)*HROWB + acol_l;
    uint32_t brow_l = (uint32_t)(((lane>>4)*8) + (lane&7));
    uint32_t bcol_l = (uint32_t)((lane&8) ? 16 : 0);
    #pragma unroll
    for (int p=0;p<2;p++)
      b_off[p] = (uint32_t)(wn*32 + p*16 + brow_l)*HROWB + bcol_l;
  }

  float4 ra[4], rb[4];
  #pragma unroll
  for (int e=0;e<4;e++){ ra[e] = *(const float4*)(aptr + e*4); rb[e] = *(const float4*)(bptr + e*4); }
  #pragma unroll
  for (int e=0;e<4;e++){
    *(uint2*)&As[0][lr][lg*16 + e*4] = f4h4(ra[e]);
    *(uint2*)&Bs[0][lr][lg*16 + e*4] = f4h4(rb[e]);
  }
  __syncthreads();

  const int KT = K >> 5;   // 24
  for (int kt=0; kt<KT; kt++){
    int buf = kt & 1;
    uint32_t baseA = sbA + buf*BUF;
    uint32_t baseB = sbB + buf*BUF;
    if (kt+1 < KT){
      #pragma unroll
      for (int e=0;e<4;e++){
        ra[e] = *(const float4*)(aptr + (kt+1)*32 + e*4);
        rb[e] = *(const float4*)(bptr + (kt+1)*32 + e*4);
      }
    }
    #pragma unroll
    for (int kk=0; kk<2; kk++){
      uint32_t kb = kk*32;
      uint32_t af[4][4], bf[2][4];
      #pragma unroll
      for (int mt=0;mt<4;mt++) ldsm4(af[mt], baseA + a_off[mt] + kb);
      #pragma unroll
      for (int p=0;p<2;p++)    ldsm4(bf[p],  baseB + b_off[p] + kb);
      #pragma unroll
      for (int mt=0;mt<4;mt++){
        mma_fp16(acc[mt][0], af[mt], bf[0][0], bf[0][1]);
        mma_fp16(acc[mt][1], af[mt], bf[0][2], bf[0][3]);
        mma_fp16(acc[mt][2], af[mt], bf[1][0], bf[1][1]);
        mma_fp16(acc[mt][3], af[mt], bf[1][2], bf[1][3]);
      }
    }
    if (kt+1 < KT){
      int nb = buf^1;
      #pragma unroll
      for (int e=0;e<4;e++){
        *(uint2*)&As[nb][lr][lg*16 + e*4] = f4h4(ra[e]);
        *(uint2*)&Bs[nb][lr][lg*16 + e*4] = f4h4(rb[e]);
      }
    }
    __syncthreads();
  }

  // scatter epilogue into q/k/v [B*H, N, 64]
  #pragma unroll
  for (int mt=0;mt<4;mt++){
    int row = bm + wm*64 + mt*16 + g;
    int n = row & 1023;
    #pragma unroll
    for (int nt=0;nt<4;nt++){
      int col = bn + wn*32 + nt*8 + 2*t;
      float bias0, bias1;
      float* dst;
      if (col < 1536){
        int part = (col >= 768) ? 1 : 0;
        int cc = col - part*768;
        int head = cc >> 6, hd = cc & 63;
        dst = (part ? vo : ko) + ((size_t)(bb*NHEADS + head)*NSEQ + n)*HDIM + hd;
        bias0 = kv_b[col]; bias1 = kv_b[col+1];
      } else if (col < 2240){
        int cc = col - 1536;
        int head = cc >> 6, hd = cc & 63;
        dst = qo + ((size_t)(bb*NHEADS + head)*NSEQ + n)*HDIM + hd;
        bias0 = sq_b[cc]; bias1 = sq_b[cc+1];
      } else {
        int hd = col - 2240;
        dst = qo + ((size_t)(bb*NHEADS + 11)*NSEQ + n)*HDIM + hd;
        bias0 = cq_b[coh*64 + hd]; bias1 = cq_b[coh*64 + hd + 1];
      }
      dst[0] = acc[mt][nt][0] + bias0;
      dst[1] = acc[mt][nt][1] + bias1;
      float* dst2 = dst + 8*HDIM;
      dst2[0] = acc[mt][nt][2] + bias0;
      dst2[1] = acc[mt][nt][3] + bias1;
    }
  }
}

// ---------------- LayerNorm ----------------
__global__ __launch_bounds__(256) void ln_kernel(const float* __restrict__ x,
    const float* __restrict__ gam, const float* __restrict__ bet, float* __restrict__ out){
  __shared__ float red[2][8];
  int row = blockIdx.x, tid = threadIdx.x;
  const float* xr = x + (size_t)row*DIMM;
  float v0 = xr[tid], v1 = xr[tid+256], v2 = xr[tid+512];
  float s = v0+v1+v2;
  float q = v0*v0 + v1*v1 + v2*v2;
  #pragma unroll
  for (int o=16;o;o>>=1){ s += __shfl_xor_sync(0xffffffffu, s, o); q += __shfl_xor_sync(0xffffffffu, q, o); }
  int wid = tid>>5, lane = tid&31;
  if (lane==0){ red[0][wid]=s; red[1][wid]=q; }
  __syncthreads();
  if (tid < 32){
    s = (lane<8)? red[0][lane] : 0.f;
    q = (lane<8)? red[1][lane] : 0.f;
    #pragma unroll
    for (int o=4;o;o>>=1){ s += __shfl_xor_sync(0xffffffffu, s, o); q += __shfl_xor_sync(0xffffffffu, q, o); }
    if (lane==0){ red[0][0]=s; red[1][0]=q; }
  }
  __syncthreads();
  float mu  = red[0][0] * (1.f/(float)DIMM);
  float var = red[1][0] * (1.f/(float)DIMM) - mu*mu;
  float rs = rsqrtf(var + 1e-5f);
  float* orow = out + (size_t)row*DIMM;
  orow[tid]     = (v0-mu)*rs*gam[tid]     + bet[tid];
  orow[tid+256] = (v1-mu)*rs*gam[tid+256] + bet[tid+256];
  orow[tid+512] = (v2-mu)*rs*gam[tid+512] + bet[tid+512];
}

// ---------------- flash attention (legacy tf32 mma, proven) ----------------
#define KS_STRIDE 68
#define VT_STRIDE 132
#define PS_STRIDE 132
__global__ __launch_bounds__(256, 1) void attn_kernel(
    const float* __restrict__ qb, const float* __restrict__ kb,
    const float* __restrict__ vb, float* __restrict__ ob){
  extern __shared__ float smatt[];
  float* KS = smatt;
  float* VT = smatt + 128*KS_STRIDE;
  float* PS = VT + 64*VT_STRIDE;
  int tid = threadIdx.x, warp = tid>>5, lane = tid&31, g = lane>>2, t = lane&3;
  int bh = blockIdx.y, qt = blockIdx.x;
  const float* Q = qb + ((size_t)bh*NSEQ + qt*128)*HDIM;
  const float* K = kb + (size_t)bh*NSEQ*HDIM;
  const float* V = vb + (size_t)bh*NSEQ*HDIM;

  for (int i=tid; i<128*16; i+=256){
    int r = i>>4, c = i&15;
    float4 v4 = *(const float4*)(Q + (size_t)r*HDIM + c*4);
    uint32_t* p = (uint32_t*)&KS[r*KS_STRIDE + c*4];
    p[0]=f2tf(v4.x*SCALEQ); p[1]=f2tf(v4.y*SCALEQ); p[2]=f2tf(v4.z*SCALEQ); p[3]=f2tf(v4.w*SCALEQ);
  }
  __syncthreads();
  uint32_t qa[8][4];
  {
    const uint32_t* ks = (const uint32_t*)KS;
    int r0 = warp*16 + g;
    #pragma unroll
    for (int k8=0;k8<8;k8++){
      qa[k8][0] = ks[(size_t)r0*KS_STRIDE     + k8*8 + t];
      qa[k8][1] = ks[(size_t)(r0+8)*KS_STRIDE + k8*8 + t];
      qa[k8][2] = ks[(size_t)r0*KS_STRIDE     + k8*8 + t + 4];
      qa[k8][3] = ks[(size_t)(r0+8)*KS_STRIDE + k8*8 + t + 4];
    }
  }
  __syncthreads();

  float m0=-1e30f, m1=-1e30f, l0=0.f, l1=0.f;
  float oa[8][4];
  #pragma unroll
  for (int dt=0;dt<8;dt++){ oa[dt][0]=0.f; oa[dt][1]=0.f; oa[dt][2]=0.f; oa[dt][3]=0.f; }

  for (int it=0; it<8; it++){
    const float* Kt = K + (size_t)it*128*HDIM;
    const float* Vt = V + (size_t)it*128*HDIM;
    for (int i=tid; i<128*16; i+=256){
      int r = i>>4, c = i&15;
      float4 v4 = *(const float4*)(Kt + (size_t)r*HDIM + c*4);
      uint32_t* p = (uint32_t*)&KS[r*KS_STRIDE + c*4];
      p[0]=f2tf(v4.x); p[1]=f2tf(v4.y); p[2]=f2tf(v4.z); p[3]=f2tf(v4.w);
    }
    {
      uint32_t* vt = (uint32_t*)VT;
      for (int i=tid; i<128*16; i+=256){
        int n = i>>4, d4 = i&15;
        float4 v4 = *(const float4*)(Vt + (size_t)n*HDIM + d4*4);
        vt[(d4*4+0)*VT_STRIDE + n] = f2tf(v4.x);
        vt[(d4*4+1)*VT_STRIDE + n] = f2tf(v4.y);
        vt[(d4*4+2)*VT_STRIDE + n] = f2tf(v4.z);
        vt[(d4*4+3)*VT_STRIDE + n] = f2tf(v4.w);
      }
    }
    __syncthreads();

    float s[16][4];
    #pragma unroll
    for (int nt=0;nt<16;nt++){ s[nt][0]=0.f; s[nt][1]=0.f; s[nt][2]=0.f; s[nt][3]=0.f; }
    {
      const uint32_t* ks = (const uint32_t*)KS;
      #pragma unroll
      for (int k8=0;k8<8;k8++){
        #pragma unroll
        for (int nt=0;nt<16;nt++){
          uint32_t b0 = ks[(size_t)(nt*8+g)*KS_STRIDE + k8*8 + t];
          uint32_t b1 = ks[(size_t)(nt*8+g)*KS_STRIDE + k8*8 + t + 4];
          mma_tf32(s[nt], qa[k8], b0, b1);
        }
      }
    }
    float mx0 = -1e30f, mx1 = -1e30f;
    #pragma unroll
    for (int nt=0;nt<16;nt++){
      mx0 = fmaxf(mx0, fmaxf(s[nt][0], s[nt][1]));
      mx1 = fmaxf(mx1, fmaxf(s[nt][2], s[nt][3]));
    }
    mx0 = fmaxf(mx0, __shfl_xor_sync(0xffffffffu, mx0, 1));
    mx0 = fmaxf(mx0, __shfl_xor_sync(0xffffffffu, mx0, 2));
    mx1 = fmaxf(mx1, __shfl_xor_sync(0xffffffffu, mx1, 1));
    mx1 = fmaxf(mx1, __shfl_xor_sync(0xffffffffu, mx1, 2));
    float nm0 = fmaxf(m0, mx0), nm1 = fmaxf(m1, mx1);
    float al0 = __expf(m0 - nm0), al1 = __expf(m1 - nm1);
    m0 = nm0; m1 = nm1;
    float sum0 = 0.f, sum1 = 0.f;
    #pragma unroll
    for (int nt=0;nt<16;nt++){
      s[nt][0] = __expf(s[nt][0] - m0);
      s[nt][1] = __expf(s[nt][1] - m0);
      s[nt][2] = __expf(s[nt][2] - m1);
      s[nt][3] = __expf(s[nt][3] - m1);
      sum0 += s[nt][0] + s[nt][1];
      sum1 += s[nt][2] + s[nt][3];
    }
    l0 = l0*al0 + sum0;
    l1 = l1*al1 + sum1;
    #pragma unroll
    for (int dt=0;dt<8;dt++){
      oa[dt][0]*=al0; oa[dt][1]*=al0; oa[dt][2]*=al1; oa[dt][3]*=al1;
    }
    uint32_t* ps = (uint32_t*)(PS + (size_t)warp*16*PS_STRIDE);
    #pragma unroll
    for (int nt=0;nt<16;nt++){
      ps[(size_t)g*PS_STRIDE     + nt*8 + 2*t]     = f2tf(s[nt][0]);
      ps[(size_t)g*PS_STRIDE     + nt*8 + 2*t + 1] = f2tf(s[nt][1]);
      ps[(size_t)(g+8)*PS_STRIDE + nt*8 + 2*t]     = f2tf(s[nt][2]);
      ps[(size_t)(g+8)*PS_STRIDE + nt*8 + 2*t + 1] = f2tf(s[nt][3]);
    }
    __syncwarp();
    {
      const uint32_t* vt = (const uint32_t*)VT;
      #pragma unroll
      for (int k2=0;k2<16;k2++){
        uint32_t pa[4];
        pa[0] = ps[(size_t)g*PS_STRIDE     + k2*8 + t];
        pa[1] = ps[(size_t)(g+8)*PS_STRIDE + k2*8 + t];
        pa[2] = ps[(size_t)g*PS_STRIDE     + k2*8 + t + 4];
        pa[3] = ps[(size_t)(g+8)*PS_STRIDE + k2*8 + t + 4];
        #pragma unroll
        for (int dt=0;dt<8;dt++){
          uint32_t b0 = vt[(size_t)(dt*8+g)*VT_STRIDE + k2*8 + t];
          uint32_t b1 = vt[(size_t)(dt*8+g)*VT_STRIDE + k2*8 + t + 4];
          mma_tf32(oa[dt], pa, b0, b1);
        }
      }
    }
    __syncthreads();
  }

  l0 += __shfl_xor_sync(0xffffffffu, l0, 1);
  l0 += __shfl_xor_sync(0xffffffffu, l0, 2);
  l1 += __shfl_xor_sync(0xffffffffu, l1, 1);
  l1 += __shfl_xor_sync(0xffffffffu, l1, 2);
  float inv0 = 1.f/l0, inv1 = 1.f/l1;

  int b = bh / NHEADS, h = bh % NHEADS;
  int row0 = qt*128 + warp*16 + g;
  float* obase = ob + (size_t)b*NSEQ*DIMM + h*HDIM;
  #pragma unroll
  for (int dt=0;dt<8;dt++){
    int col = dt*8 + 2*t;
    *(float2*)(obase + (size_t)row0*DIMM + col)     = make_float2(oa[dt][0]*inv0, oa[dt][1]*inv0);
    *(float2*)(obase + (size_t)(row0+8)*DIMM + col) = make_float2(oa[dt][2]*inv1, oa[dt][3]*inv1);
  }
}

// ---------------- host ----------------
extern "C" void kernel_launch(void* const* d_in, const int* in_sizes, int n_in,
                              void* d_out, int out_size){
  const float* x      = (const float*)d_in[0];
  const int*   cvals  = (const int*)  d_in[1];
  const float* ln1_g  = (const float*)d_in[2];
  const float* ln1_b  = (const float*)d_in[3];
  const float* kv_w   = (const float*)d_in[4];
  const float* kv_b   = (const float*)d_in[5];
  const float* sq_w   = (const float*)d_in[6];
  const float* sq_b   = (const float*)d_in[7];
  const float* cq_w   = (const float*)d_in[8];
  const float* cq_b   = (const float*)d_in[9];
  const float* proj_w = (const float*)d_in[10];
  const float* proj_b = (const float*)d_in[11];
  const float* ln2_g  = (const float*)d_in[12];
  const float* ln2_b  = (const float*)d_in[13];
  const float* fc1_w  = (const float*)d_in[14];
  const float* fc1_b  = (const float*)d_in[15];
  const float* fc2_w  = (const float*)d_in[16];
  const float* fc2_b  = (const float*)d_in[17];
  float* out = (float*)d_out;

  float *h, *q, *k, *v, *o, *x1, *h2, *mi;
  cudaGetSymbolAddress((void**)&h,  g_h);
  cudaGetSymbolAddress((void**)&q,  g_q);
  cudaGetSymbolAddress((void**)&k,  g_k);
  cudaGetSymbolAddress((void**)&v,  g_v);
  cudaGetSymbolAddress((void**)&o,  g_o);
  cudaGetSymbolAddress((void**)&x1, g_x1);
  cudaGetSymbolAddress((void**)&h2, g_h2);
  cudaGetSymbolAddress((void**)&mi, g_mi);

  // 1. LN1
  ln_kernel<<<TOKS, 256>>>(x, ln1_g, ln1_b, h);
  // 2. fused QKV (+ cohort routing) -> q/k/v [B*H, N, 64]
  qkv_fp16<<<dim3(18, 64), 256>>>(h, kv_w, sq_w, cq_w, kv_b, sq_b, cq_b, cvals, q, k, v);
  // 3. attention -> o [B, N, 768]
  size_t smem = (size_t)(128*KS_STRIDE + 64*VT_STRIDE + 8*16*PS_STRIDE) * sizeof(float);
  cudaFuncSetAttribute(attn_kernel, cudaFuncAttributeMaxDynamicSharedMemorySize, (int)smem);
  attn_kernel<<<dim3(8, 96), 256, smem>>>(q, k, v, o);
  // 4. proj + residual -> x1
  gemm_fp16<0><<<dim3(6, 64), 256>>>(o, proj_w, proj_b, x, x1, DIMM, DIMM);
  // 5. LN2
  ln_kernel<<<TOKS, 256>>>(x1, ln2_g, ln2_b, h2);
  // 6. fc1 + gelu -> mi
  gemm_fp16<1><<<dim3(24, 64), 256>>>(h2, fc1_w, fc1_b, nullptr, mi, HIDM, DIMM);
  // 7. fc2 + residual -> out
  gemm_fp16<0><<<dim3(6, 64), 256>>>(mi, fc2_w, fc2_b, x1, out, DIMM, HIDM);
}

// round 11
// speedup vs baseline: 1.3916x; 1.1548x over previous
#include <cuda_runtime.h>
#include <cuda_fp16.h>
#include <cstdint>
#include <math.h>

#define TOKS 8192
#define DIMM 768
#define HIDM 3072
#define NSEQ 1024
#define NHEADS 12
#define HDIM 64
#define SCALEQ 0.125f

// ---------------- scratch ----------------
__device__ __align__(16) __half g_hh[TOKS*DIMM];       // LN1 out (fp16)
__device__ __align__(16) __half g_h2[TOKS*DIMM];       // LN2 out (fp16)
__device__ __align__(16) __half g_o [TOKS*DIMM];       // attention out (fp16)
__device__ __align__(16) __half g_mi[TOKS*HIDM];       // fc1+gelu out (fp16)
__device__ float  g_q [96*NSEQ*HDIM];
__device__ float  g_k [96*NSEQ*HDIM];
__device__ float  g_v [96*NSEQ*HDIM];
__device__ float  g_x1[TOKS*DIMM];
// converted fp16 weights, packed
#define OFF_KV 0
#define OFF_SQ 1179648
#define OFF_CQ 1720320
#define OFF_PJ 1916928
#define OFF_F1 2506752
#define OFF_F2 4866048
#define WH_TOTAL 7225344
__device__ __align__(16) __half g_wh[WH_TOTAL];

// ---------------- helpers ----------------
__device__ __forceinline__ uint32_t f2tf(float f){
  uint32_t u; asm("cvt.rna.tf32.f32 %0, %1;" : "=r"(u) : "f"(f)); return u;
}
__device__ __forceinline__ uint32_t smem_u32(const void* p){
  uint32_t a; asm("{ .reg .u64 t; cvta.to.shared.u64 t, %1; cvt.u32.u64 %0, t; }" : "=r"(a) : "l"(p));
  return a;
}
__device__ __forceinline__ float gelu_exact(float x){
  return 0.5f * x * (1.0f + erff(x * 0.70710678118654752f));
}
__device__ __forceinline__ void mma_tf32(float c[4], const uint32_t a[4], uint32_t b0, uint32_t b1){
  asm volatile("mma.sync.aligned.m16n8k8.row.col.f32.tf32.tf32.f32 "
      "{%0,%1,%2,%3},{%4,%5,%6,%7},{%8,%9},{%0,%1,%2,%3};"
      : "+f"(c[0]), "+f"(c[1]), "+f"(c[2]), "+f"(c[3])
      : "r"(a[0]), "r"(a[1]), "r"(a[2]), "r"(a[3]), "r"(b0), "r"(b1));
}
__device__ __forceinline__ void mma_fp16(float c[4], const uint32_t a[4], uint32_t b0, uint32_t b1){
  asm volatile("mma.sync.aligned.m16n8k16.row.col.f32.f16.f16.f32 "
      "{%0,%1,%2,%3},{%4,%5,%6,%7},{%8,%9},{%0,%1,%2,%3};"
      : "+f"(c[0]), "+f"(c[1]), "+f"(c[2]), "+f"(c[3])
      : "r"(a[0]), "r"(a[1]), "r"(a[2]), "r"(a[3]), "r"(b0), "r"(b1));
}
__device__ __forceinline__ void ldsm4(uint32_t r[4], uint32_t a){
  asm volatile("ldmatrix.sync.aligned.m8n8.x4.shared.b16 {%0,%1,%2,%3}, [%4];"
    : "=r"(r[0]), "=r"(r[1]), "=r"(r[2]), "=r"(r[3]) : "r"(a));
}
__device__ __forceinline__ uint2 f4h4(float4 v){
  __half2 h01 = __float22half2_rn(make_float2(v.x, v.y));
  __half2 h23 = __float22half2_rn(make_float2(v.z, v.w));
  uint2 u;
  u.x = *(uint32_t*)&h01;
  u.y = *(uint32_t*)&h23;
  return u;
}

// smem tile: 128 rows x 40 halves (32 data + 8 pad) = 80B stride, conflict-free ldmatrix
#define HROW 40
#define HROWB 80

// ---------------- fp16 GEMM (pre-converted operands): out = A @ W^T + epi -----
// CTA 128x128, BK=32, 256 thr, warp tile 64x32, double-buffered reg-prefetch.
// MODE 0: float out = acc + bias + res   MODE 1: half out = gelu(acc + bias)
template<int MODE>
__global__ __launch_bounds__(256) void gemm_h(
    const __half* __restrict__ A, const __half* __restrict__ W,
    const float* __restrict__ bias, const float* __restrict__ res,
    void* __restrict__ outv, int Nc, int K){
  __shared__ __align__(16) __half As[2][128][HROW];
  __shared__ __align__(16) __half Bs[2][128][HROW];
  int tid = threadIdx.x;
  int warp = tid>>5, lane = tid&31, g = lane>>2, t = lane&3;
  int wm = warp>>2, wn = warp&3;
  int bm = blockIdx.y*128, bn = blockIdx.x*128;

  // loader: 2 threads per row; each thread owns 2 16B granules (32B) per operand
  int lr = tid>>1, lg = tid&1;
  const uint4* asrc = (const uint4*)(A + (size_t)(bm+lr)*K) + lg*2;
  const uint4* bsrc = (const uint4*)(W + (size_t)(bn+lr)*K) + lg*2;

  uint32_t sbA = smem_u32(&As[0][0][0]);
  uint32_t sbB = smem_u32(&Bs[0][0][0]);
  const uint32_t BUF = 128*HROWB;

  float acc[4][4][4];
  #pragma unroll
  for (int i=0;i<4;i++)
    #pragma unroll
    for (int j=0;j<4;j++){ acc[i][j][0]=0.f; acc[i][j][1]=0.f; acc[i][j][2]=0.f; acc[i][j][3]=0.f; }

  uint32_t a_off[4], b_off[2];
  {
    uint32_t arow_l = (uint32_t)(lane&15);
    uint32_t acol_l = (uint32_t)((lane>>4)*16);
    #pragma unroll
    for (int mt=0;mt<4;mt++)
      a_off[mt] = (uint32_t)(wm*64 + mt*16 + arow_l)*HROWB + acol_l;
    uint32_t brow_l = (uint32_t)(((lane>>4)*8) + (lane&7));
    uint32_t bcol_l = (uint32_t)((lane&8) ? 16 : 0);
    #pragma unroll
    for (int p=0;p<2;p++)
      b_off[p] = (uint32_t)(wn*32 + p*16 + brow_l)*HROWB + bcol_l;
  }

  // preload chunk 0 (chunk stride = 4 uint4 per row)
  uint4 ra0 = asrc[0], ra1 = asrc[1];
  uint4 rb0 = bsrc[0], rb1 = bsrc[1];
  {
    uint4* da = (uint4*)&As[0][lr][lg*16];
    uint4* db = (uint4*)&Bs[0][lr][lg*16];
    da[0]=ra0; da[1]=ra1; db[0]=rb0; db[1]=rb1;
  }
  __syncthreads();

  int KT = K >> 5;
  for (int kt=0; kt<KT; kt++){
    int buf = kt & 1;
    uint32_t baseA = sbA + buf*BUF;
    uint32_t baseB = sbB + buf*BUF;
    if (kt+1 < KT){
      ra0 = asrc[(kt+1)*4];   ra1 = asrc[(kt+1)*4+1];
      rb0 = bsrc[(kt+1)*4];   rb1 = bsrc[(kt+1)*4+1];
    }
    #pragma unroll
    for (int kk=0; kk<2; kk++){
      uint32_t kb = kk*32;
      uint32_t af[4][4], bf[2][4];
      #pragma unroll
      for (int mt=0;mt<4;mt++) ldsm4(af[mt], baseA + a_off[mt] + kb);
      #pragma unroll
      for (int p=0;p<2;p++)    ldsm4(bf[p],  baseB + b_off[p] + kb);
      #pragma unroll
      for (int mt=0;mt<4;mt++){
        mma_fp16(acc[mt][0], af[mt], bf[0][0], bf[0][1]);
        mma_fp16(acc[mt][1], af[mt], bf[0][2], bf[0][3]);
        mma_fp16(acc[mt][2], af[mt], bf[1][0], bf[1][1]);
        mma_fp16(acc[mt][3], af[mt], bf[1][2], bf[1][3]);
      }
    }
    if (kt+1 < KT){
      int nb = buf^1;
      uint4* da = (uint4*)&As[nb][lr][lg*16];
      uint4* db = (uint4*)&Bs[nb][lr][lg*16];
      da[0]=ra0; da[1]=ra1; db[0]=rb0; db[1]=rb1;
    }
    __syncthreads();
  }

  #pragma unroll
  for (int mt=0;mt<4;mt++){
    int row = bm + wm*64 + mt*16 + g;
    #pragma unroll
    for (int nt=0;nt<4;nt++){
      int col = bn + wn*32 + nt*8 + 2*t;
      float b0v = bias[col], b1v = bias[col+1];
      float v00 = acc[mt][nt][0] + b0v, v01 = acc[mt][nt][1] + b1v;
      float v10 = acc[mt][nt][2] + b0v, v11 = acc[mt][nt][3] + b1v;
      if (MODE==0){
        float* out = (float*)outv;
        const float* r0 = res + (size_t)row*Nc + col;
        const float* r1 = res + (size_t)(row+8)*Nc + col;
        v00 += r0[0]; v01 += r0[1]; v10 += r1[0]; v11 += r1[1];
        *(float2*)(out + (size_t)row*Nc + col)     = make_float2(v00,v01);
        *(float2*)(out + (size_t)(row+8)*Nc + col) = make_float2(v10,v11);
      } else {
        __half* out = (__half*)outv;
        v00 = gelu_exact(v00); v01 = gelu_exact(v01);
        v10 = gelu_exact(v10); v11 = gelu_exact(v11);
        *(__half2*)(out + (size_t)row*Nc + col)     = __floats2half2_rn(v00,v01);
        *(__half2*)(out + (size_t)(row+8)*Nc + col) = __floats2half2_rn(v10,v11);
      }
    }
  }
}

// ---------------- fp16 fused QKV: Nc=2304 = [kv 1536 | sq 704 | cohort 64] -----
__global__ __launch_bounds__(256) void qkv_h(
    const __half* __restrict__ A, const __half* __restrict__ WH,
    const float* __restrict__ kv_b, const float* __restrict__ sq_b, const float* __restrict__ cq_b,
    const int* __restrict__ cvals,
    float* __restrict__ qo, float* __restrict__ ko, float* __restrict__ vo){
  __shared__ __align__(16) __half As[2][128][HROW];
  __shared__ __align__(16) __half Bs[2][128][HROW];
  const int K = DIMM;
  int tid = threadIdx.x;
  int warp = tid>>5, lane = tid&31, g = lane>>2, t = lane&3;
  int wm = warp>>2, wn = warp&3;
  int bm = blockIdx.y*128, bn = blockIdx.x*128;
  int bb = bm >> 10;
  int coh = cvals[bb];

  int lr = tid>>1, lg = tid&1;
  const uint4* asrc = (const uint4*)(A + (size_t)(bm+lr)*K) + lg*2;
  int j = bn + lr;
  const __half* bw;
  if (j < 1536)      bw = WH + OFF_KV + (size_t)j*K;
  else if (j < 2240) bw = WH + OFF_SQ + (size_t)(j-1536)*K;
  else               bw = WH + OFF_CQ + ((size_t)coh*64 + (j-2240))*K;
  const uint4* bsrc = (const uint4*)bw + lg*2;

  uint32_t sbA = smem_u32(&As[0][0][0]);
  uint32_t sbB = smem_u32(&Bs[0][0][0]);
  const uint32_t BUF = 128*HROWB;

  float acc[4][4][4];
  #pragma unroll
  for (int i=0;i<4;i++)
    #pragma unroll
    for (int jx=0;jx<4;jx++){ acc[i][jx][0]=0.f; acc[i][jx][1]=0.f; acc[i][jx][2]=0.f; acc[i][jx][3]=0.f; }

  uint32_t a_off[4], b_off[2];
  {
    uint32_t arow_l = (uint32_t)(lane&15);
    uint32_t acol_l = (uint32_t)((lane>>4)*16);
    #pragma unroll
    for (int mt=0;mt<4;mt++)
      a_off[mt] = (uint32_t)(wm*64 + mt*16 + arow_l)*HROWB + acol_l;
    uint32_t brow_l = (uint32_t)(((lane>>4)*8) + (lane&7));
    uint32_t bcol_l = (uint32_t)((lane&8) ? 16 : 0);
    #pragma unroll
    for (int p=0;p<2;p++)
      b_off[p] = (uint32_t)(wn*32 + p*16 + brow_l)*HROWB + bcol_l;
  }

  uint4 ra0 = asrc[0], ra1 = asrc[1];
  uint4 rb0 = bsrc[0], rb1 = bsrc[1];
  {
    uint4* da = (uint4*)&As[0][lr][lg*16];
    uint4* db = (uint4*)&Bs[0][lr][lg*16];
    da[0]=ra0; da[1]=ra1; db[0]=rb0; db[1]=rb1;
  }
  __syncthreads();

  const int KT = K >> 5;  // 24
  for (int kt=0; kt<KT; kt++){
    int buf = kt & 1;
    uint32_t baseA = sbA + buf*BUF;
    uint32_t baseB = sbB + buf*BUF;
    if (kt+1 < KT){
      ra0 = asrc[(kt+1)*4];   ra1 = asrc[(kt+1)*4+1];
      rb0 = bsrc[(kt+1)*4];   rb1 = bsrc[(kt+1)*4+1];
    }
    #pragma unroll
    for (int kk=0; kk<2; kk++){
      uint32_t kb = kk*32;
      uint32_t af[4][4], bf[2][4];
      #pragma unroll
      for (int mt=0;mt<4;mt++) ldsm4(af[mt], baseA + a_off[mt] + kb);
      #pragma unroll
      for (int p=0;p<2;p++)    ldsm4(bf[p],  baseB + b_off[p] + kb);
      #pragma unroll
      for (int mt=0;mt<4;mt++){
        mma_fp16(acc[mt][0], af[mt], bf[0][0], bf[0][1]);
        mma_fp16(acc[mt][1], af[mt], bf[0][2], bf[0][3]);
        mma_fp16(acc[mt][2], af[mt], bf[1][0], bf[1][1]);
        mma_fp16(acc[mt][3], af[mt], bf[1][2], bf[1][3]);
      }
    }
    if (kt+1 < KT){
      int nb = buf^1;
      uint4* da = (uint4*)&As[nb][lr][lg*16];
      uint4* db = (uint4*)&Bs[nb][lr][lg*16];
      da[0]=ra0; da[1]=ra1; db[0]=rb0; db[1]=rb1;
    }
    __syncthreads();
  }

  // scatter epilogue into q/k/v [B*H, N, 64]
  #pragma unroll
  for (int mt=0;mt<4;mt++){
    int row = bm + wm*64 + mt*16 + g;
    int n = row & 1023;
    #pragma unroll
    for (int nt=0;nt<4;nt++){
      int col = bn + wn*32 + nt*8 + 2*t;
      float bias0, bias1;
      float* dst;
      if (col < 1536){
        int part = (col >= 768) ? 1 : 0;
        int cc = col - part*768;
        int head = cc >> 6, hd = cc & 63;
        dst = (part ? vo : ko) + ((size_t)(bb*NHEADS + head)*NSEQ + n)*HDIM + hd;
        bias0 = kv_b[col]; bias1 = kv_b[col+1];
      } else if (col < 2240){
        int cc = col - 1536;
        int head = cc >> 6, hd = cc & 63;
        dst = qo + ((size_t)(bb*NHEADS + head)*NSEQ + n)*HDIM + hd;
        bias0 = sq_b[cc]; bias1 = sq_b[cc+1];
      } else {
        int hd = col - 2240;
        dst = qo + ((size_t)(bb*NHEADS + 11)*NSEQ + n)*HDIM + hd;
        bias0 = cq_b[coh*64 + hd]; bias1 = cq_b[coh*64 + hd + 1];
      }
      dst[0] = acc[mt][nt][0] + bias0;
      dst[1] = acc[mt][nt][1] + bias1;
      float* dst2 = dst + 8*HDIM;
      dst2[0] = acc[mt][nt][2] + bias0;
      dst2[1] = acc[mt][nt][3] + bias1;
    }
  }
}

// ---------------- f32 -> f16 weight conversion ----------------
__global__ __launch_bounds__(256) void cvt_h(const float* __restrict__ in,
                                             __half* __restrict__ out, int n4){
  int i = blockIdx.x*256 + threadIdx.x;
  if (i < n4){
    float4 v = *(const float4*)(in + (size_t)i*4);
    *(uint2*)(out + (size_t)i*4) = f4h4(v);
  }
}

// ---------------- LayerNorm (fp16 out) ----------------
__global__ __launch_bounds__(256) void ln_h(const float* __restrict__ x,
    const float* __restrict__ gam, const float* __restrict__ bet, __half* __restrict__ out){
  __shared__ float red[2][8];
  int row = blockIdx.x, tid = threadIdx.x;
  const float* xr = x + (size_t)row*DIMM;
  float v0 = xr[tid], v1 = xr[tid+256], v2 = xr[tid+512];
  float s = v0+v1+v2;
  float q = v0*v0 + v1*v1 + v2*v2;
  #pragma unroll
  for (int o=16;o;o>>=1){ s += __shfl_xor_sync(0xffffffffu, s, o); q += __shfl_xor_sync(0xffffffffu, q, o); }
  int wid = tid>>5, lane = tid&31;
  if (lane==0){ red[0][wid]=s; red[1][wid]=q; }
  __syncthreads();
  if (tid < 32){
    s = (lane<8)? red[0][lane] : 0.f;
    q = (lane<8)? red[1][lane] : 0.f;
    #pragma unroll
    for (int o=4;o;o>>=1){ s += __shfl_xor_sync(0xffffffffu, s, o); q += __shfl_xor_sync(0xffffffffu, q, o); }
    if (lane==0){ red[0][0]=s; red[1][0]=q; }
  }
  __syncthreads();
  float mu  = red[0][0] * (1.f/(float)DIMM);
  float var = red[1][0] * (1.f/(float)DIMM) - mu*mu;
  float rs = rsqrtf(var + 1e-5f);
  __half* orow = out + (size_t)row*DIMM;
  orow[tid]     = __float2half_rn((v0-mu)*rs*gam[tid]     + bet[tid]);
  orow[tid+256] = __float2half_rn((v1-mu)*rs*gam[tid+256] + bet[tid+256]);
  orow[tid+512] = __float2half_rn((v2-mu)*rs*gam[tid+512] + bet[tid+512]);
}

// ---------------- flash attention (tf32 mma, fp16 output) ----------------
#define KS_STRIDE 68
#define VT_STRIDE 132
#define PS_STRIDE 132
__global__ __launch_bounds__(256, 1) void attn_kernel(
    const float* __restrict__ qb, const float* __restrict__ kb,
    const float* __restrict__ vb, __half* __restrict__ ob){
  extern __shared__ float smatt[];
  float* KS = smatt;
  float* VT = smatt + 128*KS_STRIDE;
  float* PS = VT + 64*VT_STRIDE;
  int tid = threadIdx.x, warp = tid>>5, lane = tid&31, g = lane>>2, t = lane&3;
  int bh = blockIdx.y, qt = blockIdx.x;
  const float* Q = qb + ((size_t)bh*NSEQ + qt*128)*HDIM;
  const float* K = kb + (size_t)bh*NSEQ*HDIM;
  const float* V = vb + (size_t)bh*NSEQ*HDIM;

  for (int i=tid; i<128*16; i+=256){
    int r = i>>4, c = i&15;
    float4 v4 = *(const float4*)(Q + (size_t)r*HDIM + c*4);
    uint32_t* p = (uint32_t*)&KS[r*KS_STRIDE + c*4];
    p[0]=f2tf(v4.x*SCALEQ); p[1]=f2tf(v4.y*SCALEQ); p[2]=f2tf(v4.z*SCALEQ); p[3]=f2tf(v4.w*SCALEQ);
  }
  __syncthreads();
  uint32_t qa[8][4];
  {
    const uint32_t* ks = (const uint32_t*)KS;
    int r0 = warp*16 + g;
    #pragma unroll
    for (int k8=0;k8<8;k8++){
      qa[k8][0] = ks[(size_t)r0*KS_STRIDE     + k8*8 + t];
      qa[k8][1] = ks[(size_t)(r0+8)*KS_STRIDE + k8*8 + t];
      qa[k8][2] = ks[(size_t)r0*KS_STRIDE     + k8*8 + t + 4];
      qa[k8][3] = ks[(size_t)(r0+8)*KS_STRIDE + k8*8 + t + 4];
    }
  }
  __syncthreads();

  float m0=-1e30f, m1=-1e30f, l0=0.f, l1=0.f;
  float oa[8][4];
  #pragma unroll
  for (int dt=0;dt<8;dt++){ oa[dt][0]=0.f; oa[dt][1]=0.f; oa[dt][2]=0.f; oa[dt][3]=0.f; }

  for (int it=0; it<8; it++){
    const float* Kt = K + (size_t)it*128*HDIM;
    const float* Vt = V + (size_t)it*128*HDIM;
    for (int i=tid; i<128*16; i+=256){
      int r = i>>4, c = i&15;
      float4 v4 = *(const float4*)(Kt + (size_t)r*HDIM + c*4);
      uint32_t* p = (uint32_t*)&KS[r*KS_STRIDE + c*4];
      p[0]=f2tf(v4.x); p[1]=f2tf(v4.y); p[2]=f2tf(v4.z); p[3]=f2tf(v4.w);
    }
    {
      uint32_t* vt = (uint32_t*)VT;
      for (int i=tid; i<128*16; i+=256){
        int n = i>>4, d4 = i&15;
        float4 v4 = *(const float4*)(Vt + (size_t)n*HDIM + d4*4);
        vt[(d4*4+0)*VT_STRIDE + n] = f2tf(v4.x);
        vt[(d4*4+1)*VT_STRIDE + n] = f2tf(v4.y);
        vt[(d4*4+2)*VT_STRIDE + n] = f2tf(v4.z);
        vt[(d4*4+3)*VT_STRIDE + n] = f2tf(v4.w);
      }
    }
    __syncthreads();

    float s[16][4];
    #pragma unroll
    for (int nt=0;nt<16;nt++){ s[nt][0]=0.f; s[nt][1]=0.f; s[nt][2]=0.f; s[nt][3]=0.f; }
    {
      const uint32_t* ks = (const uint32_t*)KS;
      #pragma unroll
      for (int k8=0;k8<8;k8++){
        #pragma unroll
        for (int nt=0;nt<16;nt++){
          uint32_t b0 = ks[(size_t)(nt*8+g)*KS_STRIDE + k8*8 + t];
          uint32_t b1 = ks[(size_t)(nt*8+g)*KS_STRIDE + k8*8 + t + 4];
          mma_tf32(s[nt], qa[k8], b0, b1);
        }
      }
    }
    float mx0 = -1e30f, mx1 = -1e30f;
    #pragma unroll
    for (int nt=0;nt<16;nt++){
      mx0 = fmaxf(mx0, fmaxf(s[nt][0], s[nt][1]));
      mx1 = fmaxf(mx1, fmaxf(s[nt][2], s[nt][3]));
    }
    mx0 = fmaxf(mx0, __shfl_xor_sync(0xffffffffu, mx0, 1));
    mx0 = fmaxf(mx0, __shfl_xor_sync(0xffffffffu, mx0, 2));
    mx1 = fmaxf(mx1, __shfl_xor_sync(0xffffffffu, mx1, 1));
    mx1 = fmaxf(mx1, __shfl_xor_sync(0xffffffffu, mx1, 2));
    float nm0 = fmaxf(m0, mx0), nm1 = fmaxf(m1, mx1);
    float al0 = __expf(m0 - nm0), al1 = __expf(m1 - nm1);
    m0 = nm0; m1 = nm1;
    float sum0 = 0.f, sum1 = 0.f;
    #pragma unroll
    for (int nt=0;nt<16;nt++){
      s[nt][0] = __expf(s[nt][0] - m0);
      s[nt][1] = __expf(s[nt][1] - m0);
      s[nt][2] = __expf(s[nt][2] - m1);
      s[nt][3] = __expf(s[nt][3] - m1);
      sum0 += s[nt][0] + s[nt][1];
      sum1 += s[nt][2] + s[nt][3];
    }
    l0 = l0*al0 + sum0;
    l1 = l1*al1 + sum1;
    #pragma unroll
    for (int dt=0;dt<8;dt++){
      oa[dt][0]*=al0; oa[dt][1]*=al0; oa[dt][2]*=al1; oa[dt][3]*=al1;
    }
    uint32_t* ps = (uint32_t*)(PS + (size_t)warp*16*PS_STRIDE);
    #pragma unroll
    for (int nt=0;nt<16;nt++){
      ps[(size_t)g*PS_STRIDE     + nt*8 + 2*t]     = f2tf(s[nt][0]);
      ps[(size_t)g*PS_STRIDE     + nt*8 + 2*t + 1] = f2tf(s[nt][1]);
      ps[(size_t)(g+8)*PS_STRIDE + nt*8 + 2*t]     = f2tf(s[nt][2]);
      ps[(size_t)(g+8)*PS_STRIDE + nt*8 + 2*t + 1] = f2tf(s[nt][3]);
    }
    __syncwarp();
    {
      const uint32_t* vt = (const uint32_t*)VT;
      #pragma unroll
      for (int k2=0;k2<16;k2++){
        uint32_t pa[4];
        pa[0] = ps[(size_t)g*PS_STRIDE     + k2*8 + t];
        pa[1] = ps[(size_t)(g+8)*PS_STRIDE + k2*8 + t];
        pa[2] = ps[(size_t)g*PS_STRIDE     + k2*8 + t + 4];
        pa[3] = ps[(size_t)(g+8)*PS_STRIDE + k2*8 + t + 4];
        #pragma unroll
        for (int dt=0;dt<8;dt++){
          uint32_t b0 = vt[(size_t)(dt*8+g)*VT_STRIDE + k2*8 + t];
          uint32_t b1 = vt[(size_t)(dt*8+g)*VT_STRIDE + k2*8 + t + 4];
          mma_tf32(oa[dt], pa, b0, b1);
        }
      }
    }
    __syncthreads();
  }

  l0 += __shfl_xor_sync(0xffffffffu, l0, 1);
  l0 += __shfl_xor_sync(0xffffffffu, l0, 2);
  l1 += __shfl_xor_sync(0xffffffffu, l1, 1);
  l1 += __shfl_xor_sync(0xffffffffu, l1, 2);
  float inv0 = 1.f/l0, inv1 = 1.f/l1;

  int b = bh / NHEADS, h = bh % NHEADS;
  int row0 = qt*128 + warp*16 + g;
  __half* obase = ob + (size_t)b*NSEQ*DIMM + h*HDIM;
  #pragma unroll
  for (int dt=0;dt<8;dt++){
    int col = dt*8 + 2*t;
    *(__half2*)(obase + (size_t)row0*DIMM + col)     = __floats2half2_rn(oa[dt][0]*inv0, oa[dt][1]*inv0);
    *(__half2*)(obase + (size_t)(row0+8)*DIMM + col) = __floats2half2_rn(oa[dt][2]*inv1, oa[dt][3]*inv1);
  }
}

// ---------------- host ----------------
extern "C" void kernel_launch(void* const* d_in, const int* in_sizes, int n_in,
                              void* d_out, int out_size){
  const float* x      = (const float*)d_in[0];
  const int*   cvals  = (const int*)  d_in[1];
  const float* ln1_g  = (const float*)d_in[2];
  const float* ln1_b  = (const float*)d_in[3];
  const float* kv_w   = (const float*)d_in[4];
  const float* kv_b   = (const float*)d_in[5];
  const float* sq_w   = (const float*)d_in[6];
  const float* sq_b   = (const float*)d_in[7];
  const float* cq_w   = (const float*)d_in[8];
  const float* cq_b   = (const float*)d_in[9];
  const float* proj_w = (const float*)d_in[10];
  const float* proj_b = (const float*)d_in[11];
  const float* ln2_g  = (const float*)d_in[12];
  const float* ln2_b  = (const float*)d_in[13];
  const float* fc1_w  = (const float*)d_in[14];
  const float* fc1_b  = (const float*)d_in[15];
  const float* fc2_w  = (const float*)d_in[16];
  const float* fc2_b  = (const float*)d_in[17];
  float* out = (float*)d_out;

  __half *hh, *h2, *o, *mi, *wh;
  float *q, *k, *v, *x1;
  cudaGetSymbolAddress((void**)&hh, g_hh);
  cudaGetSymbolAddress((void**)&h2, g_h2);
  cudaGetSymbolAddress((void**)&o,  g_o);
  cudaGetSymbolAddress((void**)&mi, g_mi);
  cudaGetSymbolAddress((void**)&wh, g_wh);
  cudaGetSymbolAddress((void**)&q,  g_q);
  cudaGetSymbolAddress((void**)&k,  g_k);
  cudaGetSymbolAddress((void**)&v,  g_v);
  cudaGetSymbolAddress((void**)&x1, g_x1);

  // 0. convert weights to fp16 (once per launch; deterministic)
  cvt_h<<<(1536*768/4+255)/256, 256>>>(kv_w,   wh+OFF_KV, 1536*768/4);
  cvt_h<<<( 704*768/4+255)/256, 256>>>(sq_w,   wh+OFF_SQ,  704*768/4);
  cvt_h<<<(4*64*768/4+255)/256, 256>>>(cq_w,   wh+OFF_CQ, 4*64*768/4);
  cvt_h<<<( 768*768/4+255)/256, 256>>>(proj_w, wh+OFF_PJ,  768*768/4);
  cvt_h<<<(3072*768/4+255)/256, 256>>>(fc1_w,  wh+OFF_F1, 3072*768/4);
  cvt_h<<<(768*3072/4+255)/256, 256>>>(fc2_w,  wh+OFF_F2,  768*3072/4);

  // 1. LN1 -> fp16
  ln_h<<<TOKS, 256>>>(x, ln1_g, ln1_b, hh);
  // 2. fused QKV (+ cohort routing) -> q/k/v f32 [B*H, N, 64]
  qkv_h<<<dim3(18, 64), 256>>>(hh, wh, kv_b, sq_b, cq_b, cvals, q, k, v);
  // 3. attention -> o fp16 [B, N, 768]
  size_t smem = (size_t)(128*KS_STRIDE + 64*VT_STRIDE + 8*16*PS_STRIDE) * sizeof(float);
  cudaFuncSetAttribute(attn_kernel, cudaFuncAttributeMaxDynamicSharedMemorySize, (int)smem);
  attn_kernel<<<dim3(8, 96), 256, smem>>>(q, k, v, o);
  // 4. proj + residual -> x1 f32
  gemm_h<0><<<dim3(6, 64), 256>>>(o, wh+OFF_PJ, proj_b, x, x1, DIMM, DIMM);
  // 5. LN2 -> fp16
  ln_h<<<TOKS, 256>>>(x1, ln2_g, ln2_b, h2);
  // 6. fc1 + gelu -> mi fp16
  gemm_h<1><<<dim3(24, 64), 256>>>(h2, wh+OFF_F1, fc1_b, nullptr, mi, HIDM, DIMM);
  // 7. fc2 + residual -> out f32
  gemm_h<0><<<dim3(6, 64), 256>>>(mi, wh+OFF_F2, fc2_b, x1, out, DIMM, HIDM);
}

// round 13
// speedup vs baseline: 1.6016x; 1.1509x over previous
#include <cuda_runtime.h>
#include <cuda_fp16.h>
#include <cstdint>
#include <math.h>

#define TOKS 8192
#define DIMM 768
#define HIDM 3072
#define NSEQ 1024
#define NHEADS 12
#define HDIM 64
#define SCALEQ 0.125f

// ---------------- scratch ----------------
__device__ __align__(16) __half g_hh[TOKS*DIMM];       // LN1 out (fp16)
__device__ __align__(16) __half g_h2[TOKS*DIMM];       // LN2 out (fp16)
__device__ __align__(16) __half g_o [TOKS*DIMM];       // attention out (fp16)
__device__ __align__(16) __half g_mi[TOKS*HIDM];       // fc1+gelu out (fp16)
__device__ __align__(16) __half g_q [96*NSEQ*HDIM];
__device__ __align__(16) __half g_k [96*NSEQ*HDIM];
__device__ __align__(16) __half g_v [96*NSEQ*HDIM];
__device__ float  g_x1[TOKS*DIMM];
// converted fp16 weights, packed
#define OFF_KV 0
#define OFF_SQ 1179648
#define OFF_CQ 1720320
#define OFF_PJ 1916928
#define OFF_F1 2506752
#define OFF_F2 4866048
#define WH_TOTAL 7225344
__device__ __align__(16) __half g_wh[WH_TOTAL];

// ---------------- helpers ----------------
__device__ __forceinline__ uint32_t smem_u32(const void* p){
  uint32_t a; asm("{ .reg .u64 t; cvta.to.shared.u64 t, %1; cvt.u32.u64 %0, t; }" : "=r"(a) : "l"(p));
  return a;
}
__device__ __forceinline__ float gelu_exact(float x){
  return 0.5f * x * (1.0f + erff(x * 0.70710678118654752f));
}
__device__ __forceinline__ void mma_fp16(float c[4], const uint32_t a[4], uint32_t b0, uint32_t b1){
  asm volatile("mma.sync.aligned.m16n8k16.row.col.f32.f16.f16.f32 "
      "{%0,%1,%2,%3},{%4,%5,%6,%7},{%8,%9},{%0,%1,%2,%3};"
      : "+f"(c[0]), "+f"(c[1]), "+f"(c[2]), "+f"(c[3])
      : "r"(a[0]), "r"(a[1]), "r"(a[2]), "r"(a[3]), "r"(b0), "r"(b1));
}
__device__ __forceinline__ void ldsm4(uint32_t r[4], uint32_t a){
  asm volatile("ldmatrix.sync.aligned.m8n8.x4.shared.b16 {%0,%1,%2,%3}, [%4];"
    : "=r"(r[0]), "=r"(r[1]), "=r"(r[2]), "=r"(r[3]) : "r"(a));
}
__device__ __forceinline__ uint2 f4h4(float4 v){
  __half2 h01 = __float22half2_rn(make_float2(v.x, v.y));
  __half2 h23 = __float22half2_rn(make_float2(v.z, v.w));
  uint2 u;
  u.x = *(uint32_t*)&h01;
  u.y = *(uint32_t*)&h23;
  return u;
}

// smem tile: 128 rows x 40 halves (32 data + 8 pad) = 80B stride, conflict-free ldmatrix
#define HROW 40
#define HROWB 80

// ---------------- fp16 GEMM (pre-converted operands): out = A @ W^T + epi -----
// CTA 128x128, BK=32, 256 thr, warp tile 64x32, double-buffered reg-prefetch.
// MODE 0: float out = acc + bias + res   MODE 1: half out = gelu(acc + bias)
template<int MODE>
__global__ __launch_bounds__(256) void gemm_h(
    const __half* __restrict__ A, const __half* __restrict__ W,
    const float* __restrict__ bias, const float* __restrict__ res,
    void* __restrict__ outv, int Nc, int K){
  __shared__ __align__(16) __half As[2][128][HROW];
  __shared__ __align__(16) __half Bs[2][128][HROW];
  int tid = threadIdx.x;
  int warp = tid>>5, lane = tid&31, g = lane>>2, t = lane&3;
  int wm = warp>>2, wn = warp&3;
  int bm = blockIdx.y*128, bn = blockIdx.x*128;

  int lr = tid>>1, lg = tid&1;
  const uint4* asrc = (const uint4*)(A + (size_t)(bm+lr)*K) + lg*2;
  const uint4* bsrc = (const uint4*)(W + (size_t)(bn+lr)*K) + lg*2;

  uint32_t sbA = smem_u32(&As[0][0][0]);
  uint32_t sbB = smem_u32(&Bs[0][0][0]);
  const uint32_t BUF = 128*HROWB;

  float acc[4][4][4];
  #pragma unroll
  for (int i=0;i<4;i++)
    #pragma unroll
    for (int j=0;j<4;j++){ acc[i][j][0]=0.f; acc[i][j][1]=0.f; acc[i][j][2]=0.f; acc[i][j][3]=0.f; }

  uint32_t a_off[4], b_off[2];
  {
    uint32_t arow_l = (uint32_t)(lane&15);
    uint32_t acol_l = (uint32_t)((lane>>4)*16);
    #pragma unroll
    for (int mt=0;mt<4;mt++)
      a_off[mt] = (uint32_t)(wm*64 + mt*16 + arow_l)*HROWB + acol_l;
    uint32_t brow_l = (uint32_t)(((lane>>4)*8) + (lane&7));
    uint32_t bcol_l = (uint32_t)((lane&8) ? 16 : 0);
    #pragma unroll
    for (int p=0;p<2;p++)
      b_off[p] = (uint32_t)(wn*32 + p*16 + brow_l)*HROWB + bcol_l;
  }

  uint4 ra0 = asrc[0], ra1 = asrc[1];
  uint4 rb0 = bsrc[0], rb1 = bsrc[1];
  {
    uint4* da = (uint4*)&As[0][lr][lg*16];
    uint4* db = (uint4*)&Bs[0][lr][lg*16];
    da[0]=ra0; da[1]=ra1; db[0]=rb0; db[1]=rb1;
  }
  __syncthreads();

  int KT = K >> 5;
  for (int kt=0; kt<KT; kt++){
    int buf = kt & 1;
    uint32_t baseA = sbA + buf*BUF;
    uint32_t baseB = sbB + buf*BUF;
    if (kt+1 < KT){
      ra0 = asrc[(kt+1)*4];   ra1 = asrc[(kt+1)*4+1];
      rb0 = bsrc[(kt+1)*4];   rb1 = bsrc[(kt+1)*4+1];
    }
    #pragma unroll
    for (int kk=0; kk<2; kk++){
      uint32_t kb = kk*32;
      uint32_t af[4][4], bf[2][4];
      #pragma unroll
      for (int mt=0;mt<4;mt++) ldsm4(af[mt], baseA + a_off[mt] + kb);
      #pragma unroll
      for (int p=0;p<2;p++)    ldsm4(bf[p],  baseB + b_off[p] + kb);
      #pragma unroll
      for (int mt=0;mt<4;mt++){
        mma_fp16(acc[mt][0], af[mt], bf[0][0], bf[0][1]);
        mma_fp16(acc[mt][1], af[mt], bf[0][2], bf[0][3]);
        mma_fp16(acc[mt][2], af[mt], bf[1][0], bf[1][1]);
        mma_fp16(acc[mt][3], af[mt], bf[1][2], bf[1][3]);
      }
    }
    if (kt+1 < KT){
      int nb = buf^1;
      uint4* da = (uint4*)&As[nb][lr][lg*16];
      uint4* db = (uint4*)&Bs[nb][lr][lg*16];
      da[0]=ra0; da[1]=ra1; db[0]=rb0; db[1]=rb1;
    }
    __syncthreads();
  }

  #pragma unroll
  for (int mt=0;mt<4;mt++){
    int row = bm + wm*64 + mt*16 + g;
    #pragma unroll
    for (int nt=0;nt<4;nt++){
      int col = bn + wn*32 + nt*8 + 2*t;
      float b0v = bias[col], b1v = bias[col+1];
      float v00 = acc[mt][nt][0] + b0v, v01 = acc[mt][nt][1] + b1v;
      float v10 = acc[mt][nt][2] + b0v, v11 = acc[mt][nt][3] + b1v;
      if (MODE==0){
        float* out = (float*)outv;
        const float* r0 = res + (size_t)row*Nc + col;
        const float* r1 = res + (size_t)(row+8)*Nc + col;
        v00 += r0[0]; v01 += r0[1]; v10 += r1[0]; v11 += r1[1];
        *(float2*)(out + (size_t)row*Nc + col)     = make_float2(v00,v01);
        *(float2*)(out + (size_t)(row+8)*Nc + col) = make_float2(v10,v11);
      } else {
        __half* out = (__half*)outv;
        v00 = gelu_exact(v00); v01 = gelu_exact(v01);
        v10 = gelu_exact(v10); v11 = gelu_exact(v11);
        *(__half2*)(out + (size_t)row*Nc + col)     = __floats2half2_rn(v00,v01);
        *(__half2*)(out + (size_t)(row+8)*Nc + col) = __floats2half2_rn(v10,v11);
      }
    }
  }
}

// ---------------- fp16 fused QKV -> fp16 q/k/v: Nc=2304 ------------------------
__global__ __launch_bounds__(256) void qkv_h(
    const __half* __restrict__ A, const __half* __restrict__ WH,
    const float* __restrict__ kv_b, const float* __restrict__ sq_b, const float* __restrict__ cq_b,
    const int* __restrict__ cvals,
    __half* __restrict__ qo, __half* __restrict__ ko, __half* __restrict__ vo){
  __shared__ __align__(16) __half As[2][128][HROW];
  __shared__ __align__(16) __half Bs[2][128][HROW];
  const int K = DIMM;
  int tid = threadIdx.x;
  int warp = tid>>5, lane = tid&31, g = lane>>2, t = lane&3;
  int wm = warp>>2, wn = warp&3;
  int bm = blockIdx.y*128, bn = blockIdx.x*128;
  int bb = bm >> 10;
  int coh = cvals[bb];

  int lr = tid>>1, lg = tid&1;
  const uint4* asrc = (const uint4*)(A + (size_t)(bm+lr)*K) + lg*2;
  int j = bn + lr;
  const __half* bw;
  if (j < 1536)      bw = WH + OFF_KV + (size_t)j*K;
  else if (j < 2240) bw = WH + OFF_SQ + (size_t)(j-1536)*K;
  else               bw = WH + OFF_CQ + ((size_t)coh*64 + (j-2240))*K;
  const uint4* bsrc = (const uint4*)bw + lg*2;

  uint32_t sbA = smem_u32(&As[0][0][0]);
  uint32_t sbB = smem_u32(&Bs[0][0][0]);
  const uint32_t BUF = 128*HROWB;

  float acc[4][4][4];
  #pragma unroll
  for (int i=0;i<4;i++)
    #pragma unroll
    for (int jx=0;jx<4;jx++){ acc[i][jx][0]=0.f; acc[i][jx][1]=0.f; acc[i][jx][2]=0.f; acc[i][jx][3]=0.f; }

  uint32_t a_off[4], b_off[2];
  {
    uint32_t arow_l = (uint32_t)(lane&15);
    uint32_t acol_l = (uint32_t)((lane>>4)*16);
    #pragma unroll
    for (int mt=0;mt<4;mt++)
      a_off[mt] = (uint32_t)(wm*64 + mt*16 + arow_l)*HROWB + acol_l;
    uint32_t brow_l = (uint32_t)(((lane>>4)*8) + (lane&7));
    uint32_t bcol_l = (uint32_t)((lane&8) ? 16 : 0);
    #pragma unroll
    for (int p=0;p<2;p++)
      b_off[p] = (uint32_t)(wn*32 + p*16 + brow_l)*HROWB + bcol_l;
  }

  uint4 ra0 = asrc[0], ra1 = asrc[1];
  uint4 rb0 = bsrc[0], rb1 = bsrc[1];
  {
    uint4* da = (uint4*)&As[0][lr][lg*16];
    uint4* db = (uint4*)&Bs[0][lr][lg*16];
    da[0]=ra0; da[1]=ra1; db[0]=rb0; db[1]=rb1;
  }
  __syncthreads();

  const int KT = K >> 5;  // 24
  for (int kt=0; kt<KT; kt++){
    int buf = kt & 1;
    uint32_t baseA = sbA + buf*BUF;
    uint32_t baseB = sbB + buf*BUF;
    if (kt+1 < KT){
      ra0 = asrc[(kt+1)*4];   ra1 = asrc[(kt+1)*4+1];
      rb0 = bsrc[(kt+1)*4];   rb1 = bsrc[(kt+1)*4+1];
    }
    #pragma unroll
    for (int kk=0; kk<2; kk++){
      uint32_t kb = kk*32;
      uint32_t af[4][4], bf[2][4];
      #pragma unroll
      for (int mt=0;mt<4;mt++) ldsm4(af[mt], baseA + a_off[mt] + kb);
      #pragma unroll
      for (int p=0;p<2;p++)    ldsm4(bf[p],  baseB + b_off[p] + kb);
      #pragma unroll
      for (int mt=0;mt<4;mt++){
        mma_fp16(acc[mt][0], af[mt], bf[0][0], bf[0][1]);
        mma_fp16(acc[mt][1], af[mt], bf[0][2], bf[0][3]);
        mma_fp16(acc[mt][2], af[mt], bf[1][0], bf[1][1]);
        mma_fp16(acc[mt][3], af[mt], bf[1][2], bf[1][3]);
      }
    }
    if (kt+1 < KT){
      int nb = buf^1;
      uint4* da = (uint4*)&As[nb][lr][lg*16];
      uint4* db = (uint4*)&Bs[nb][lr][lg*16];
      da[0]=ra0; da[1]=ra1; db[0]=rb0; db[1]=rb1;
    }
    __syncthreads();
  }

  // scatter epilogue into fp16 q/k/v [B*H, N, 64]
  #pragma unroll
  for (int mt=0;mt<4;mt++){
    int row = bm + wm*64 + mt*16 + g;
    int n = row & 1023;
    #pragma unroll
    for (int nt=0;nt<4;nt++){
      int col = bn + wn*32 + nt*8 + 2*t;
      float bias0, bias1;
      __half* dst;
      if (col < 1536){
        int part = (col >= 768) ? 1 : 0;
        int cc = col - part*768;
        int head = cc >> 6, hd = cc & 63;
        dst = (part ? vo : ko) + ((size_t)(bb*NHEADS + head)*NSEQ + n)*HDIM + hd;
        bias0 = kv_b[col]; bias1 = kv_b[col+1];
      } else if (col < 2240){
        int cc = col - 1536;
        int head = cc >> 6, hd = cc & 63;
        dst = qo + ((size_t)(bb*NHEADS + head)*NSEQ + n)*HDIM + hd;
        bias0 = sq_b[cc]; bias1 = sq_b[cc+1];
      } else {
        int hd = col - 2240;
        dst = qo + ((size_t)(bb*NHEADS + 11)*NSEQ + n)*HDIM + hd;
        bias0 = cq_b[coh*64 + hd]; bias1 = cq_b[coh*64 + hd + 1];
      }
      *(__half2*)dst = __floats2half2_rn(acc[mt][nt][0] + bias0, acc[mt][nt][1] + bias1);
      *(__half2*)(dst + 8*HDIM) = __floats2half2_rn(acc[mt][nt][2] + bias0, acc[mt][nt][3] + bias1);
    }
  }
}

// ---------------- f32 -> f16 weight conversion ----------------
__global__ __launch_bounds__(256) void cvt_h(const float* __restrict__ in,
                                             __half* __restrict__ out, int n4){
  int i = blockIdx.x*256 + threadIdx.x;
  if (i < n4){
    float4 v = *(const float4*)(in + (size_t)i*4);
    *(uint2*)(out + (size_t)i*4) = f4h4(v);
  }
}

// ---------------- LayerNorm (fp16 out) ----------------
__global__ __launch_bounds__(256) void ln_h(const float* __restrict__ x,
    const float* __restrict__ gam, const float* __restrict__ bet, __half* __restrict__ out){
  __shared__ float red[2][8];
  int row = blockIdx.x, tid = threadIdx.x;
  const float* xr = x + (size_t)row*DIMM;
  float v0 = xr[tid], v1 = xr[tid+256], v2 = xr[tid+512];
  float s = v0+v1+v2;
  float q = v0*v0 + v1*v1 + v2*v2;
  #pragma unroll
  for (int o=16;o;o>>=1){ s += __shfl_xor_sync(0xffffffffu, s, o); q += __shfl_xor_sync(0xffffffffu, q, o); }
  int wid = tid>>5, lane = tid&31;
  if (lane==0){ red[0][wid]=s; red[1][wid]=q; }
  __syncthreads();
  if (tid < 32){
    s = (lane<8)? red[0][lane] : 0.f;
    q = (lane<8)? red[1][lane] : 0.f;
    #pragma unroll
    for (int o=4;o;o>>=1){ s += __shfl_xor_sync(0xffffffffu, s, o); q += __shfl_xor_sync(0xffffffffu, q, o); }
    if (lane==0){ red[0][0]=s; red[1][0]=q; }
  }
  __syncthreads();
  float mu  = red[0][0] * (1.f/(float)DIMM);
  float var = red[1][0] * (1.f/(float)DIMM) - mu*mu;
  float rs = rsqrtf(var + 1e-5f);
  __half* orow = out + (size_t)row*DIMM;
  orow[tid]     = __float2half_rn((v0-mu)*rs*gam[tid]     + bet[tid]);
  orow[tid+256] = __float2half_rn((v1-mu)*rs*gam[tid+256] + bet[tid+256]);
  orow[tid+512] = __float2half_rn((v2-mu)*rs*gam[tid+512] + bet[tid+512]);
}

// ---------------- flash attention, fp16 mma + ldmatrix ----------------
// smem (bytes): KS [128][72]h @0 (18432) | VT [64][136]h @18432 (17408) | PS 8x[16][136]h @35840 (34816)
#define ATT_VT 18432
#define ATT_PS 35840
#define ATT_SMEM 70656
__global__ __launch_bounds__(256, 1) void attn_h(
    const __half* __restrict__ qb, const __half* __restrict__ kb,
    const __half* __restrict__ vb, __half* __restrict__ ob){
  extern __shared__ __align__(16) char sm[];
  uint32_t sb = smem_u32(sm);
  int tid = threadIdx.x, warp = tid>>5, lane = tid&31, g = lane>>2, t = lane&3;
  int bh = blockIdx.y, qt = blockIdx.x;
  const __half* Q = qb + ((size_t)bh*NSEQ + qt*128)*HDIM;
  const __half* K = kb + (size_t)bh*NSEQ*HDIM;
  const __half* V = vb + (size_t)bh*NSEQ*HDIM;

  uint32_t arow_l = (uint32_t)(lane&15);
  uint32_t acol_l = (uint32_t)((lane>>4)*16);
  uint32_t brow_l = (uint32_t)(((lane>>4)*8) + (lane&7));
  uint32_t bcol_l = (uint32_t)((lane&8) ? 16 : 0);

  // stage Q into KS area (row stride 144B), pull A-fragments (K=64 -> 4 chunks)
  for (int i=tid; i<1024; i+=256){
    int r = i>>3, c = (i&7)*8;
    *(uint4*)(sm + r*144 + c*2) = *(const uint4*)(Q + (size_t)r*HDIM + c);
  }
  __syncthreads();
  uint32_t qa[4][4];
  #pragma unroll
  for (int kc=0;kc<4;kc++)
    ldsm4(qa[kc], sb + (uint32_t)(warp*16 + arow_l)*144 + acol_l + kc*32);
  __syncthreads();

  float m0=-1e30f, m1=-1e30f, l0=0.f, l1=0.f;
  float oa[8][4];
  #pragma unroll
  for (int dt=0;dt<8;dt++){ oa[dt][0]=0.f; oa[dt][1]=0.f; oa[dt][2]=0.f; oa[dt][3]=0.f; }

  for (int it=0; it<8; it++){
    const __half* Kt = K + (size_t)it*128*HDIM;
    const __half* Vt = V + (size_t)it*128*HDIM;
    // K tile -> KS (row stride 144B)
    for (int i=tid; i<1024; i+=256){
      int r = i>>3, c = (i&7)*8;
      *(uint4*)(sm + r*144 + c*2) = *(const uint4*)(Kt + (size_t)r*HDIM + c);
    }
    // V transposed -> VT[d][key], row stride 272B
    for (int i=tid; i<1024; i+=256){
      int key = i & 127, d8 = (i>>7)<<3;
      uint4 vv = *(const uint4*)(Vt + (size_t)key*HDIM + d8);
      const __half* hp = (const __half*)&vv;
      #pragma unroll
      for (int jj=0;jj<8;jj++)
        *(__half*)(sm + ATT_VT + (d8+jj)*272 + key*2) = hp[jj];
    }
    __syncthreads();

    // S = Q K^T : per warp 16 rows x 128 keys, K=64
    float s[16][4];
    #pragma unroll
    for (int nt=0;nt<16;nt++){ s[nt][0]=0.f; s[nt][1]=0.f; s[nt][2]=0.f; s[nt][3]=0.f; }
    #pragma unroll
    for (int kc=0;kc<4;kc++){
      #pragma unroll
      for (int p=0;p<8;p++){
        uint32_t bf[4];
        ldsm4(bf, sb + (uint32_t)(p*16 + brow_l)*144 + bcol_l + kc*32);
        mma_fp16(s[2*p],   qa[kc], bf[0], bf[1]);
        mma_fp16(s[2*p+1], qa[kc], bf[2], bf[3]);
      }
    }
    // scale (2^-3, exact)
    #pragma unroll
    for (int nt=0;nt<16;nt++){
      s[nt][0]*=SCALEQ; s[nt][1]*=SCALEQ; s[nt][2]*=SCALEQ; s[nt][3]*=SCALEQ;
    }
    // online softmax
    float mx0 = -1e30f, mx1 = -1e30f;
    #pragma unroll
    for (int nt=0;nt<16;nt++){
      mx0 = fmaxf(mx0, fmaxf(s[nt][0], s[nt][1]));
      mx1 = fmaxf(mx1, fmaxf(s[nt][2], s[nt][3]));
    }
    mx0 = fmaxf(mx0, __shfl_xor_sync(0xffffffffu, mx0, 1));
    mx0 = fmaxf(mx0, __shfl_xor_sync(0xffffffffu, mx0, 2));
    mx1 = fmaxf(mx1, __shfl_xor_sync(0xffffffffu, mx1, 1));
    mx1 = fmaxf(mx1, __shfl_xor_sync(0xffffffffu, mx1, 2));
    float nm0 = fmaxf(m0, mx0), nm1 = fmaxf(m1, mx1);
    float al0 = __expf(m0 - nm0), al1 = __expf(m1 - nm1);
    m0 = nm0; m1 = nm1;
    float sum0 = 0.f, sum1 = 0.f;
    #pragma unroll
    for (int nt=0;nt<16;nt++){
      s[nt][0] = __expf(s[nt][0] - m0);
      s[nt][1] = __expf(s[nt][1] - m0);
      s[nt][2] = __expf(s[nt][2] - m1);
      s[nt][3] = __expf(s[nt][3] - m1);
      sum0 += s[nt][0] + s[nt][1];
      sum1 += s[nt][2] + s[nt][3];
    }
    l0 = l0*al0 + sum0;
    l1 = l1*al1 + sum1;
    #pragma unroll
    for (int dt=0;dt<8;dt++){
      oa[dt][0]*=al0; oa[dt][1]*=al0; oa[dt][2]*=al1; oa[dt][3]*=al1;
    }
    // P (half) -> per-warp PS [16][136]h, row stride 272B
    {
      char* psw = sm + ATT_PS + warp*4352;
      #pragma unroll
      for (int nt=0;nt<16;nt++){
        *(__half2*)(psw + g*272     + (nt*8 + 2*t)*2) = __floats2half2_rn(s[nt][0], s[nt][1]);
        *(__half2*)(psw + (g+8)*272 + (nt*8 + 2*t)*2) = __floats2half2_rn(s[nt][2], s[nt][3]);
      }
    }
    __syncwarp();
    // O += P V : per warp 16 rows x 64 dims, K=128 keys (8 chunks)
    {
      uint32_t psb = sb + ATT_PS + warp*4352;
      #pragma unroll
      for (int kc=0;kc<8;kc++){
        uint32_t pa[4];
        ldsm4(pa, psb + arow_l*272 + acol_l + kc*32);
        #pragma unroll
        for (int p=0;p<4;p++){
          uint32_t bf[4];
          ldsm4(bf, sb + ATT_VT + (uint32_t)(p*16 + brow_l)*272 + bcol_l + kc*32);
          mma_fp16(oa[2*p],   pa, bf[0], bf[1]);
          mma_fp16(oa[2*p+1], pa, bf[2], bf[3]);
        }
      }
    }
    __syncthreads();
  }

  l0 += __shfl_xor_sync(0xffffffffu, l0, 1);
  l0 += __shfl_xor_sync(0xffffffffu, l0, 2);
  l1 += __shfl_xor_sync(0xffffffffu, l1, 1);
  l1 += __shfl_xor_sync(0xffffffffu, l1, 2);
  float inv0 = 1.f/l0, inv1 = 1.f/l1;

  int b = bh / NHEADS, h = bh % NHEADS;
  int row0 = qt*128 + warp*16 + g;
  __half* obase = ob + (size_t)b*NSEQ*DIMM + h*HDIM;
  #pragma unroll
  for (int dt=0;dt<8;dt++){
    int col = dt*8 + 2*t;
    *(__half2*)(obase + (size_t)row0*DIMM + col)     = __floats2half2_rn(oa[dt][0]*inv0, oa[dt][1]*inv0);
    *(__half2*)(obase + (size_t)(row0+8)*DIMM + col) = __floats2half2_rn(oa[dt][2]*inv1, oa[dt][3]*inv1);
  }
}

// ---------------- host ----------------
extern "C" void kernel_launch(void* const* d_in, const int* in_sizes, int n_in,
                              void* d_out, int out_size){
  const float* x      = (const float*)d_in[0];
  const int*   cvals  = (const int*)  d_in[1];
  const float* ln1_g  = (const float*)d_in[2];
  const float* ln1_b  = (const float*)d_in[3];
  const float* kv_w   = (const float*)d_in[4];
  const float* kv_b   = (const float*)d_in[5];
  const float* sq_w   = (const float*)d_in[6];
  const float* sq_b   = (const float*)d_in[7];
  const float* cq_w   = (const float*)d_in[8];
  const float* cq_b   = (const float*)d_in[9];
  const float* proj_w = (const float*)d_in[10];
  const float* proj_b = (const float*)d_in[11];
  const float* ln2_g  = (const float*)d_in[12];
  const float* ln2_b  = (const float*)d_in[13];
  const float* fc1_w  = (const float*)d_in[14];
  const float* fc1_b  = (const float*)d_in[15];
  const float* fc2_w  = (const float*)d_in[16];
  const float* fc2_b  = (const float*)d_in[17];
  float* out = (float*)d_out;

  __half *hh, *h2, *o, *mi, *wh, *q, *k, *v;
  float *x1;
  cudaGetSymbolAddress((void**)&hh, g_hh);
  cudaGetSymbolAddress((void**)&h2, g_h2);
  cudaGetSymbolAddress((void**)&o,  g_o);
  cudaGetSymbolAddress((void**)&mi, g_mi);
  cudaGetSymbolAddress((void**)&wh, g_wh);
  cudaGetSymbolAddress((void**)&q,  g_q);
  cudaGetSymbolAddress((void**)&k,  g_k);
  cudaGetSymbolAddress((void**)&v,  g_v);
  cudaGetSymbolAddress((void**)&x1, g_x1);

  // 0. convert weights to fp16 (once per launch; deterministic)
  cvt_h<<<(1536*768/4+255)/256, 256>>>(kv_w,   wh+OFF_KV, 1536*768/4);
  cvt_h<<<( 704*768/4+255)/256, 256>>>(sq_w,   wh+OFF_SQ,  704*768/4);
  cvt_h<<<(4*64*768/4+255)/256, 256>>>(cq_w,   wh+OFF_CQ, 4*64*768/4);
  cvt_h<<<( 768*768/4+255)/256, 256>>>(proj_w, wh+OFF_PJ,  768*768/4);
  cvt_h<<<(3072*768/4+255)/256, 256>>>(fc1_w,  wh+OFF_F1, 3072*768/4);
  cvt_h<<<(768*3072/4+255)/256, 256>>>(fc2_w,  wh+OFF_F2,  768*3072/4);

  // 1. LN1 -> fp16
  ln_h<<<TOKS, 256>>>(x, ln1_g, ln1_b, hh);
  // 2. fused QKV (+ cohort routing) -> fp16 q/k/v [B*H, N, 64]
  qkv_h<<<dim3(18, 64), 256>>>(hh, wh, kv_b, sq_b, cq_b, cvals, q, k, v);
  // 3. attention (fp16 mma) -> o fp16 [B, N, 768]
  cudaFuncSetAttribute(attn_h, cudaFuncAttributeMaxDynamicSharedMemorySize, ATT_SMEM);
  attn_h<<<dim3(8, 96), 256, ATT_SMEM>>>(q, k, v, o);
  // 4. proj + residual -> x1 f32
  gemm_h<0><<<dim3(6, 64), 256>>>(o, wh+OFF_PJ, proj_b, x, x1, DIMM, DIMM);
  // 5. LN2 -> fp16
  ln_h<<<TOKS, 256>>>(x1, ln2_g, ln2_b, h2);
  // 6. fc1 + gelu -> mi fp16
  gemm_h<1><<<dim3(24, 64), 256>>>(h2, wh+OFF_F1, fc1_b, nullptr, mi, HIDM, DIMM);
  // 7. fc2 + residual -> out f32
  gemm_h<0><<<dim3(6, 64), 256>>>(mi, wh+OFF_F2, fc2_b, x1, out, DIMM, HIDM);
}